// round 2
// baseline (speedup 1.0000x reference)
#include <cuda_runtime.h>
#include <math.h>

// Problem dims (fixed)
#define B_    4
#define N_    1024
#define D_    256
#define H_    8
#define HD_   32
#define FFN_  1024
#define ROWS  (B_*N_)          // 4096
#define LN_EPS 1e-5f

// ---------------- scratch (static device memory; no allocs) ----------------
__device__ float g_qksum[ROWS*D_];     // embed + query_pos
__device__ float g_qk   [ROWS*2*D_];   // per row: [q(256) | k(256)]
__device__ float g_v    [ROWS*D_];
__device__ float g_tau  [B_*H_*N_];    // (b,h,i)
__device__ float g_ctx  [ROWS*D_];
__device__ float g_x    [ROWS*D_];     // after LN1
__device__ float g_h    [ROWS*FFN_];   // relu(ffn1)
__device__ float g_y    [ROWS*D_];     // generic GEMM output

// ---------------- elementwise add: qksum = embed + query_pos ---------------
__global__ void addvec_kernel(const float* __restrict__ a, const float* __restrict__ b,
                              float* __restrict__ c, int n4) {
    int i = blockIdx.x * blockDim.x + threadIdx.x;
    if (i < n4) {
        float4 av = ((const float4*)a)[i];
        float4 bv = ((const float4*)b)[i];
        float4 cv = {av.x+bv.x, av.y+bv.y, av.z+bv.z, av.w+bv.w};
        ((float4*)c)[i] = cv;
    }
}

// ---------------- generic tiled SGEMM: C = act(A @ W^T + bias) -------------
// A[M,K] row-major, W[Nc,K] row-major, C[M,Nc]. M%64==0, Nc%64==0, K%16==0.
#define BM 64
#define BN 64
#define BK 16
__global__ __launch_bounds__(256) void gemm_kernel(
    const float* __restrict__ A, const float* __restrict__ W,
    const float* __restrict__ bias, float* __restrict__ C,
    int M, int Nc, int K, int relu)
{
    __shared__ float As[BK][BM];
    __shared__ float Bs[BK][BN];
    const int tid = threadIdx.x;
    const int tx = tid & 15, ty = tid >> 4;
    const int bm = blockIdx.y * BM, bn = blockIdx.x * BN;
    const int lr = tid >> 2;          // 0..63 tile row
    const int lc = (tid & 3) * 4;     // 0,4,8,12 within BK

    float acc[4][4] = {};
    for (int k0 = 0; k0 < K; k0 += BK) {
        float4 a = *(const float4*)&A[(bm + lr) * K + k0 + lc];
        float4 w = *(const float4*)&W[(bn + lr) * K + k0 + lc];
        As[lc+0][lr] = a.x; As[lc+1][lr] = a.y; As[lc+2][lr] = a.z; As[lc+3][lr] = a.w;
        Bs[lc+0][lr] = w.x; Bs[lc+1][lr] = w.y; Bs[lc+2][lr] = w.z; Bs[lc+3][lr] = w.w;
        __syncthreads();
        #pragma unroll
        for (int kk = 0; kk < BK; kk++) {
            float4 av = *(const float4*)&As[kk][ty*4];
            float4 bv = *(const float4*)&Bs[kk][tx*4];
            acc[0][0] += av.x*bv.x; acc[0][1] += av.x*bv.y; acc[0][2] += av.x*bv.z; acc[0][3] += av.x*bv.w;
            acc[1][0] += av.y*bv.x; acc[1][1] += av.y*bv.y; acc[1][2] += av.y*bv.z; acc[1][3] += av.y*bv.w;
            acc[2][0] += av.z*bv.x; acc[2][1] += av.z*bv.y; acc[2][2] += av.z*bv.z; acc[2][3] += av.z*bv.w;
            acc[3][0] += av.w*bv.x; acc[3][1] += av.w*bv.y; acc[3][2] += av.w*bv.z; acc[3][3] += av.w*bv.w;
        }
        __syncthreads();
    }
    #pragma unroll
    for (int i = 0; i < 4; i++) {
        #pragma unroll
        for (int j = 0; j < 4; j++) {
            float v = acc[i][j] + bias[bn + tx*4 + j];
            if (relu) v = fmaxf(v, 0.0f);
            C[(bm + ty*4 + i) * Nc + bn + tx*4 + j] = v;
        }
    }
}

// ---------------- tau: tau[b,h,i] = embed[b,i,:] . tau_w[h,:] + tau_b[h] ---
__global__ __launch_bounds__(256) void tau_kernel(
    const float* __restrict__ embed, const float* __restrict__ tw,
    const float* __restrict__ tb, float* __restrict__ tau)
{
    const int row = blockIdx.x;            // 0..4095 = b*N+i
    const int b = row >> 10, i = row & 1023;
    const int wid = threadIdx.x >> 5, lane = threadIdx.x & 31;
    const float* e = &embed[row * D_];
    const float* w = &tw[wid * D_];
    float s = 0.f;
    #pragma unroll
    for (int d = lane; d < D_; d += 32) s += e[d] * w[d];
    #pragma unroll
    for (int o = 16; o; o >>= 1) s += __shfl_xor_sync(0xffffffffu, s, o);
    if (lane == 0) tau[(b * H_ + wid) * N_ + i] = s + tb[wid];
}

// ---------------- attention: full score rows in SMEM, exact softmax --------
// grid (N/BQ, B*H), 256 threads. SMEM: S[BQ][SROW] + Q + Ktile + Vtile.
#define BQ 32
#define TJ 64
#define SROW 1032      // 1024 + 8 pad to spread banks
__global__ __launch_bounds__(256) void attn_kernel(
    const float* __restrict__ qk, const float* __restrict__ vbuf,
    const float* __restrict__ tau, const float* __restrict__ dist,
    float* __restrict__ ctx)
{
    extern __shared__ float sm[];
    float* S  = sm;                         // [BQ][SROW]
    float* Qs = S  + BQ * SROW;             // [BQ][33]
    float* Ks = Qs + BQ * 33;               // [TJ][33]
    float* Vs = Ks + TJ * 33;               // [TJ][32]
    __shared__ float taus[BQ];

    const int bh = blockIdx.y;
    const int b = bh >> 3, h = bh & 7;
    const int i0 = blockIdx.x * BQ;
    const int tid = threadIdx.x;

    for (int e = tid; e < BQ * HD_; e += 256) {
        int r = e >> 5, d = e & 31;
        Qs[r * 33 + d] = qk[(size_t)((b * N_ + i0 + r) * (2 * D_)) + h * HD_ + d];
    }
    if (tid < BQ) taus[tid] = tau[(b * H_ + h) * N_ + i0 + tid];
    __syncthreads();

    const float scale = 0.17677669529663688f;  // 1/sqrt(32)
    const int r  = tid >> 3;    // 0..31 query row
    const int cg = tid & 7;     // col group of 8

    // --- S = Q @ K^T * scale + dist*tau ---
    for (int j0 = 0; j0 < N_; j0 += TJ) {
        for (int e = tid; e < TJ * HD_; e += 256) {
            int jr = e >> 5, d = e & 31;
            Ks[jr * 33 + d] = qk[(size_t)((b * N_ + j0 + jr) * (2 * D_)) + D_ + h * HD_ + d];
        }
        __syncthreads();
        float acc[8] = {};
        #pragma unroll 8
        for (int d = 0; d < HD_; d++) {
            float qv = Qs[r * 33 + d];
            #pragma unroll
            for (int j = 0; j < 8; j++)
                acc[j] += qv * Ks[(cg * 8 + j) * 33 + d];
        }
        const float* drow = &dist[((size_t)(b * N_ + i0 + r)) * N_ + j0];
        const float tv = taus[r];
        #pragma unroll
        for (int j = 0; j < 8; j++)
            S[r * SROW + j0 + cg * 8 + j] = acc[j] * scale + drow[cg * 8 + j] * tv;
        __syncthreads();
    }

    // --- softmax per row (warp per 4 rows) ---
    {
        const int wid = tid >> 5, lane = tid & 31;
        for (int rr = wid; rr < BQ; rr += 8) {
            float* row = &S[rr * SROW];
            float m = -1e30f;
            for (int j = lane; j < N_; j += 32) m = fmaxf(m, row[j]);
            #pragma unroll
            for (int o = 16; o; o >>= 1) m = fmaxf(m, __shfl_xor_sync(0xffffffffu, m, o));
            float s = 0.f;
            for (int j = lane; j < N_; j += 32) {
                float e = __expf(row[j] - m);
                row[j] = e; s += e;
            }
            #pragma unroll
            for (int o = 16; o; o >>= 1) s += __shfl_xor_sync(0xffffffffu, s, o);
            float inv = 1.0f / s;
            for (int j = lane; j < N_; j += 32) row[j] *= inv;
        }
    }
    __syncthreads();

    // --- O = P @ V ---
    const int dg = tid & 7;     // 4 dims: dg*4..dg*4+3
    float o0 = 0.f, o1 = 0.f, o2 = 0.f, o3 = 0.f;
    for (int j0 = 0; j0 < N_; j0 += TJ) {
        for (int e = tid; e < TJ * HD_; e += 256) {
            int jr = e >> 5, d = e & 31;
            Vs[jr * 32 + d] = vbuf[(size_t)((b * N_ + j0 + jr) * D_) + h * HD_ + d];
        }
        __syncthreads();
        #pragma unroll 4
        for (int j = 0; j < TJ; j++) {
            float p = S[r * SROW + j0 + j];
            float4 vv = *(const float4*)&Vs[j * 32 + dg * 4];
            o0 += p * vv.x; o1 += p * vv.y; o2 += p * vv.z; o3 += p * vv.w;
        }
        __syncthreads();
    }
    float4 res = {o0, o1, o2, o3};
    *(float4*)&ctx[(size_t)((b * N_ + i0 + r) * D_) + h * HD_ + dg * 4] = res;
}

// ---------------- fused add + layernorm ------------------------------------
__global__ __launch_bounds__(256) void add_ln_kernel(
    const float* __restrict__ A, const float* __restrict__ Bv,
    const float* __restrict__ g, const float* __restrict__ beta,
    float* __restrict__ out)
{
    const int row = blockIdx.x;
    const int t = threadIdx.x;
    float v = A[row * D_ + t] + Bv[row * D_ + t];
    float s = v, sq = v * v;
    #pragma unroll
    for (int o = 16; o; o >>= 1) {
        s  += __shfl_xor_sync(0xffffffffu, s,  o);
        sq += __shfl_xor_sync(0xffffffffu, sq, o);
    }
    __shared__ float ss[8], ssq[8];
    if ((t & 31) == 0) { ss[t >> 5] = s; ssq[t >> 5] = sq; }
    __syncthreads();
    float tot = 0.f, totq = 0.f;
    #pragma unroll
    for (int w = 0; w < 8; w++) { tot += ss[w]; totq += ssq[w]; }
    float mean = tot * (1.0f / D_);
    float var  = totq * (1.0f / D_) - mean * mean;
    out[row * D_ + t] = (v - mean) * rsqrtf(var + LN_EPS) * g[t] + beta[t];
}

// ---------------- launch ----------------------------------------------------
extern "C" void kernel_launch(void* const* d_in, const int* in_sizes, int n_in,
                              void* d_out, int out_size)
{
    const float* embed     = (const float*)d_in[0];
    // d_in[1] = refer_bbox (unused)
    const float* dist      = (const float*)d_in[2];
    const float* query_pos = (const float*)d_in[3];
    const float* in_proj_w = (const float*)d_in[4];
    const float* in_proj_b = (const float*)d_in[5];
    const float* out_w     = (const float*)d_in[6];
    const float* out_b     = (const float*)d_in[7];
    const float* tau_w     = (const float*)d_in[8];
    const float* tau_b     = (const float*)d_in[9];
    const float* w1        = (const float*)d_in[10];
    const float* b1        = (const float*)d_in[11];
    const float* w2        = (const float*)d_in[12];
    const float* b2        = (const float*)d_in[13];
    const float* g1        = (const float*)d_in[14];
    const float* beta1     = (const float*)d_in[15];
    const float* g2        = (const float*)d_in[16];
    const float* beta2     = (const float*)d_in[17];
    float* out = (float*)d_out;

    float *p_qksum, *p_qk, *p_v, *p_tau, *p_ctx, *p_x, *p_h, *p_y;
    cudaGetSymbolAddress((void**)&p_qksum, g_qksum);
    cudaGetSymbolAddress((void**)&p_qk,    g_qk);
    cudaGetSymbolAddress((void**)&p_v,     g_v);
    cudaGetSymbolAddress((void**)&p_tau,   g_tau);
    cudaGetSymbolAddress((void**)&p_ctx,   g_ctx);
    cudaGetSymbolAddress((void**)&p_x,     g_x);
    cudaGetSymbolAddress((void**)&p_h,     g_h);
    cudaGetSymbolAddress((void**)&p_y,     g_y);

    // 1. qksum = embed + query_pos
    {
        int n4 = ROWS * D_ / 4;
        addvec_kernel<<<(n4 + 255) / 256, 256>>>(embed, query_pos, p_qksum, n4);
    }
    // 2. [q|k] = qksum @ in_proj_w[0:512].T + b[0:512]
    gemm_kernel<<<dim3(512 / BN, ROWS / BM), 256>>>(p_qksum, in_proj_w, in_proj_b, p_qk,
                                                    ROWS, 512, D_, 0);
    // 3. v = embed @ wv.T + bv
    gemm_kernel<<<dim3(D_ / BN, ROWS / BM), 256>>>(embed, in_proj_w + 512 * D_,
                                                   in_proj_b + 512, p_v, ROWS, D_, D_, 0);
    // 4. tau
    tau_kernel<<<ROWS, 256>>>(embed, tau_w, tau_b, p_tau);
    // 5. attention
    {
        int smem = (BQ * SROW + BQ * 33 + TJ * 33 + TJ * 32) * (int)sizeof(float);
        cudaFuncSetAttribute(attn_kernel, cudaFuncAttributeMaxDynamicSharedMemorySize, smem);
        attn_kernel<<<dim3(N_ / BQ, B_ * H_), 256, smem>>>(p_qk, p_v, p_tau, dist, p_ctx);
    }
    // 6. tgt = ctx @ out_w.T + out_b
    gemm_kernel<<<dim3(D_ / BN, ROWS / BM), 256>>>(p_ctx, out_w, out_b, p_y, ROWS, D_, D_, 0);
    // 7. x = LN1(embed + tgt)
    add_ln_kernel<<<ROWS, 256>>>(embed, p_y, g1, beta1, p_x);
    // 8. h = relu(x @ w1.T + b1)
    gemm_kernel<<<dim3(FFN_ / BN, ROWS / BM), 256>>>(p_x, w1, b1, p_h, ROWS, FFN_, D_, 1);
    // 9. y = h @ w2.T + b2
    gemm_kernel<<<dim3(D_ / BN, ROWS / BM), 256>>>(p_h, w2, b2, p_y, ROWS, D_, FFN_, 0);
    // 10. out = LN2(x + y)
    add_ln_kernel<<<ROWS, 256>>>(p_x, p_y, g2, beta2, out);
}

// round 4
// speedup vs baseline: 2.7032x; 2.7032x over previous
#include <cuda_runtime.h>
#include <math.h>
#include <stdint.h>

// Problem dims (fixed)
#define B_    4
#define N_    1024
#define D_    256
#define H_    8
#define HD_   32
#define FFN_  1024
#define ROWS  (B_*N_)          // 4096
#define LN_EPS 1e-5f

// ---------------- scratch (static device memory; no allocs) ----------------
__device__ float g_qk   [ROWS*2*D_];   // per row: [q(256) | k(256)]
__device__ float g_v    [ROWS*D_];
__device__ float g_tau  [B_*H_*N_];    // (b,h,i)
__device__ float g_ctx  [ROWS*D_];
__device__ float g_x    [ROWS*D_];     // after LN1
__device__ float g_h    [ROWS*FFN_];   // relu(ffn1)
__device__ float g_y    [ROWS*D_];     // generic GEMM output

// ---------------- tf32 helpers ---------------------------------------------
__device__ __forceinline__ uint32_t f2tf32(float x) {
    uint32_t r;
    asm("cvt.rna.tf32.f32 %0, %1;" : "=r"(r) : "f"(x));
    return r;
}

// D = A(m16k8,row) * B(k8n8,col) + D   (tf32 in, f32 accum)
__device__ __forceinline__ void mma8(float* c, const uint32_t* a, uint32_t b0, uint32_t b1) {
    asm volatile(
        "mma.sync.aligned.m16n8k8.row.col.f32.tf32.tf32.f32 "
        "{%0,%1,%2,%3}, {%4,%5,%6,%7}, {%8,%9}, {%0,%1,%2,%3};\n"
        : "+f"(c[0]), "+f"(c[1]), "+f"(c[2]), "+f"(c[3])
        : "r"(a[0]), "r"(a[1]), "r"(a[2]), "r"(a[3]), "r"(b0), "r"(b1));
}

// ---------------- tensor-core SGEMM: C = act(A(+A2) @ W^T + bias) ----------
// A[M,K], W[Nc,K] row-major. M%64==0, Nc%128==0, K%32==0.
#define GBM 64
#define GBN 128
#define GBK 32
#define GST 36   // smem row stride (words): bank = (4g+t) -> conflict-free frags
__global__ __launch_bounds__(256) void mma_gemm_kernel(
    const float* __restrict__ A, const float* __restrict__ A2,
    const float* __restrict__ W, const float* __restrict__ bias,
    float* __restrict__ C, int M, int Nc, int K, int relu)
{
    __shared__ uint32_t As[GBM * GST];   // 9.2 KB
    __shared__ uint32_t Ws[GBN * GST];   // 18.4 KB
    const int tid = threadIdx.x;
    const int warp = tid >> 5, lane = tid & 31;
    const int grp = lane >> 2, t4 = lane & 3;
    const int wm = warp >> 2, wn = warp & 3;      // 2 x 4 warp grid
    const int bm = blockIdx.y * GBM, bn = blockIdx.x * GBN;

    float acc[2][4][4] = {};

    for (int k0 = 0; k0 < K; k0 += GBK) {
        // stage A: 64x32 floats (2 float4 per thread)
        #pragma unroll
        for (int rep = 0; rep < 2; rep++) {
            int idx = tid + rep * 256;
            int r = idx >> 3, c4 = (idx & 7) * 4;
            float4 v = *(const float4*)&A[(size_t)(bm + r) * K + k0 + c4];
            if (A2) {
                float4 u = *(const float4*)&A2[(size_t)(bm + r) * K + k0 + c4];
                v.x += u.x; v.y += u.y; v.z += u.z; v.w += u.w;
            }
            As[r * GST + c4 + 0] = f2tf32(v.x);
            As[r * GST + c4 + 1] = f2tf32(v.y);
            As[r * GST + c4 + 2] = f2tf32(v.z);
            As[r * GST + c4 + 3] = f2tf32(v.w);
        }
        // stage W: 128x32 floats (4 float4 per thread)
        #pragma unroll
        for (int rep = 0; rep < 4; rep++) {
            int idx = tid + rep * 256;
            int r = idx >> 3, c4 = (idx & 7) * 4;
            float4 v = *(const float4*)&W[(size_t)(bn + r) * K + k0 + c4];
            Ws[r * GST + c4 + 0] = f2tf32(v.x);
            Ws[r * GST + c4 + 1] = f2tf32(v.y);
            Ws[r * GST + c4 + 2] = f2tf32(v.z);
            Ws[r * GST + c4 + 3] = f2tf32(v.w);
        }
        __syncthreads();
        #pragma unroll
        for (int kk = 0; kk < 4; kk++) {
            const int kb = kk * 8;
            uint32_t afr[2][4];
            #pragma unroll
            for (int mf = 0; mf < 2; mf++) {
                int rb = wm * 32 + mf * 16;
                afr[mf][0] = As[(rb + grp) * GST + kb + t4];
                afr[mf][1] = As[(rb + grp + 8) * GST + kb + t4];
                afr[mf][2] = As[(rb + grp) * GST + kb + t4 + 4];
                afr[mf][3] = As[(rb + grp + 8) * GST + kb + t4 + 4];
            }
            #pragma unroll
            for (int nf = 0; nf < 4; nf++) {
                int nrow = wn * 32 + nf * 8 + grp;
                uint32_t b0 = Ws[nrow * GST + kb + t4];
                uint32_t b1 = Ws[nrow * GST + kb + t4 + 4];
                mma8(acc[0][nf], afr[0], b0, b1);
                mma8(acc[1][nf], afr[1], b0, b1);
            }
        }
        __syncthreads();
    }
    #pragma unroll
    for (int mf = 0; mf < 2; mf++) {
        int r0 = bm + wm * 32 + mf * 16 + grp;
        #pragma unroll
        for (int nf = 0; nf < 4; nf++) {
            int c0 = bn + wn * 32 + nf * 8 + 2 * t4;
            float b0v = bias[c0], b1v = bias[c0 + 1];
            float v0 = acc[mf][nf][0] + b0v, v1 = acc[mf][nf][1] + b1v;
            float v2 = acc[mf][nf][2] + b0v, v3 = acc[mf][nf][3] + b1v;
            if (relu) {
                v0 = fmaxf(v0, 0.f); v1 = fmaxf(v1, 0.f);
                v2 = fmaxf(v2, 0.f); v3 = fmaxf(v3, 0.f);
            }
            float2 p0 = {v0, v1}, p1 = {v2, v3};
            *(float2*)&C[(size_t)r0 * Nc + c0] = p0;
            *(float2*)&C[(size_t)(r0 + 8) * Nc + c0] = p1;
        }
    }
}

// ---------------- tau: tau[b,h,i] = embed[b,i,:] . tau_w[h,:] + tau_b[h] ---
__global__ __launch_bounds__(256) void tau_kernel(
    const float* __restrict__ embed, const float* __restrict__ tw,
    const float* __restrict__ tb, float* __restrict__ tau)
{
    const int row = blockIdx.x;            // b*N+i
    const int b = row >> 10, i = row & 1023;
    const int wid = threadIdx.x >> 5, lane = threadIdx.x & 31;
    const float* e = &embed[row * D_];
    const float* w = &tw[wid * D_];
    float s = 0.f;
    #pragma unroll
    for (int d = lane; d < D_; d += 32) s += e[d] * w[d];
    #pragma unroll
    for (int o = 16; o; o >>= 1) s += __shfl_xor_sync(0xffffffffu, s, o);
    if (lane == 0) tau[(b * H_ + wid) * N_ + i] = s + tb[wid];
}

// ---------------- attention (tensor core), full rows in SMEM ---------------
// grid (N/32, B*H), 256 threads. S rows stride 1028 (bank map 4g+t).
#define AQ 32
#define AJ 128
#define SS 1028
__global__ __launch_bounds__(256) void attn_kernel(
    const float* __restrict__ qk, const float* __restrict__ vbuf,
    const float* __restrict__ tau, const float* __restrict__ dist,
    float* __restrict__ ctx)
{
    extern __shared__ float sm[];
    float*    S  = sm;                          // [32][1028] scores -> probs(tf32)
    uint32_t* Qs = (uint32_t*)(S + AQ * SS);    // [32][36]
    uint32_t* KV = Qs + AQ * GST;               // [128][36]
    __shared__ float invs[AQ];

    const int bh = blockIdx.y;
    const int b = bh >> 3, h = bh & 7;
    const int i0 = blockIdx.x * AQ;
    const int tid = threadIdx.x;
    const int warp = tid >> 5, lane = tid & 31;
    const int grp = lane >> 2, t4 = lane & 3;

    // stage Q (32x32), tf32
    {
        int r = tid >> 3, c4 = (tid & 7) * 4;
        float4 v = *(const float4*)&qk[(size_t)(b * N_ + i0 + r) * (2 * D_) + h * HD_ + c4];
        Qs[r * GST + c4 + 0] = f2tf32(v.x);
        Qs[r * GST + c4 + 1] = f2tf32(v.y);
        Qs[r * GST + c4 + 2] = f2tf32(v.z);
        Qs[r * GST + c4 + 3] = f2tf32(v.w);
    }
    __syncthreads();

    // ---- S = Q @ K^T (raw) ----
    const int wm = warp >> 2;          // m16 half
    const int wn = warp & 3;           // n32 quarter of 128
    for (int j0 = 0; j0 < N_; j0 += AJ) {
        #pragma unroll
        for (int rep = 0; rep < 4; rep++) {
            int idx = tid + rep * 256;
            int jr = idx >> 3, c4 = (idx & 7) * 4;
            float4 v = *(const float4*)&qk[(size_t)(b * N_ + j0 + jr) * (2 * D_) + D_ + h * HD_ + c4];
            KV[jr * GST + c4 + 0] = f2tf32(v.x);
            KV[jr * GST + c4 + 1] = f2tf32(v.y);
            KV[jr * GST + c4 + 2] = f2tf32(v.z);
            KV[jr * GST + c4 + 3] = f2tf32(v.w);
        }
        __syncthreads();

        float acc[4][4] = {};
        #pragma unroll
        for (int kk = 0; kk < 4; kk++) {
            const int kb = kk * 8;
            uint32_t a[4];
            int rb = wm * 16;
            a[0] = Qs[(rb + grp) * GST + kb + t4];
            a[1] = Qs[(rb + grp + 8) * GST + kb + t4];
            a[2] = Qs[(rb + grp) * GST + kb + t4 + 4];
            a[3] = Qs[(rb + grp + 8) * GST + kb + t4 + 4];
            #pragma unroll
            for (int nf = 0; nf < 4; nf++) {
                int nrow = wn * 32 + nf * 8 + grp;
                uint32_t b0 = KV[nrow * GST + kb + t4];
                uint32_t b1 = KV[nrow * GST + kb + t4 + 4];
                mma8(acc[nf], a, b0, b1);
            }
        }
        // write raw scores to S
        int r0 = wm * 16 + grp;
        #pragma unroll
        for (int nf = 0; nf < 4; nf++) {
            int c0 = j0 + wn * 32 + nf * 8 + 2 * t4;
            float2 p0 = {acc[nf][0], acc[nf][1]};
            float2 p1 = {acc[nf][2], acc[nf][3]};
            *(float2*)&S[r0 * SS + c0] = p0;
            *(float2*)&S[(r0 + 8) * SS + c0] = p1;
        }
        __syncthreads();
    }

    // ---- softmax per row: bias fused, store exp as tf32, keep 1/sum ----
    const float scale = 0.17677669529663688f;   // 1/sqrt(32)
    for (int rr = 0; rr < 4; rr++) {
        int row = warp + rr * 8;
        float tauv = tau[(b * H_ + h) * N_ + i0 + row];
        const float* drow = &dist[(size_t)(b * N_ + i0 + row) * N_];
        float* srow = &S[row * SS];
        float m = -1e30f;
        for (int j = lane; j < N_; j += 32) {
            float v = srow[j] * scale + drow[j] * tauv;
            srow[j] = v;
            m = fmaxf(m, v);
        }
        #pragma unroll
        for (int o = 16; o; o >>= 1) m = fmaxf(m, __shfl_xor_sync(0xffffffffu, m, o));
        float s = 0.f;
        for (int j = lane; j < N_; j += 32) {
            float e = __expf(srow[j] - m);
            s += e;
            ((uint32_t*)srow)[j] = f2tf32(e);
        }
        #pragma unroll
        for (int o = 16; o; o >>= 1) s += __shfl_xor_sync(0xffffffffu, s, o);
        if (lane == 0) invs[row] = 1.0f / s;
    }
    __syncthreads();

    // ---- O = P @ V, fold 1/sum into epilogue ----
    // warp tile: m16 (wm) x n8 (wn8), k loops all 1024
    const int wn8 = warp & 3;
    float o[4] = {};
    for (int j0 = 0; j0 < N_; j0 += AJ) {
        #pragma unroll
        for (int rep = 0; rep < 4; rep++) {
            int idx = tid + rep * 256;
            int jr = idx >> 3, c4 = (idx & 7) * 4;
            float4 v = *(const float4*)&vbuf[(size_t)(b * N_ + j0 + jr) * D_ + h * HD_ + c4];
            KV[jr * GST + c4 + 0] = f2tf32(v.x);
            KV[jr * GST + c4 + 1] = f2tf32(v.y);
            KV[jr * GST + c4 + 2] = f2tf32(v.z);
            KV[jr * GST + c4 + 3] = f2tf32(v.w);
        }
        __syncthreads();
        #pragma unroll
        for (int ks = 0; ks < AJ / 8; ks++) {
            const int kb = ks * 8;
            uint32_t a[4];
            const uint32_t* Su = (const uint32_t*)S;
            int rb = wm * 16;
            a[0] = Su[(rb + grp) * SS + j0 + kb + t4];
            a[1] = Su[(rb + grp + 8) * SS + j0 + kb + t4];
            a[2] = Su[(rb + grp) * SS + j0 + kb + t4 + 4];
            a[3] = Su[(rb + grp + 8) * SS + j0 + kb + t4 + 4];
            uint32_t b0 = KV[(kb + t4) * GST + wn8 * 8 + grp];
            uint32_t b1 = KV[(kb + t4 + 4) * GST + wn8 * 8 + grp];
            mma8(o, a, b0, b1);
        }
        __syncthreads();
    }
    {
        int rl0 = wm * 16 + grp;
        float is0 = invs[rl0], is1 = invs[rl0 + 8];
        int d0 = wn8 * 8 + 2 * t4;
        float2 p0 = {o[0] * is0, o[1] * is0};
        float2 p1 = {o[2] * is1, o[3] * is1};
        *(float2*)&ctx[(size_t)(b * N_ + i0 + rl0) * D_ + h * HD_ + d0] = p0;
        *(float2*)&ctx[(size_t)(b * N_ + i0 + rl0 + 8) * D_ + h * HD_ + d0] = p1;
    }
}

// ---------------- fused add + layernorm ------------------------------------
__global__ __launch_bounds__(256) void add_ln_kernel(
    const float* __restrict__ A, const float* __restrict__ Bv,
    const float* __restrict__ g, const float* __restrict__ beta,
    float* __restrict__ out)
{
    const int row = blockIdx.x;
    const int t = threadIdx.x;
    float v = A[row * D_ + t] + Bv[row * D_ + t];
    float s = v, sq = v * v;
    #pragma unroll
    for (int o = 16; o; o >>= 1) {
        s  += __shfl_xor_sync(0xffffffffu, s,  o);
        sq += __shfl_xor_sync(0xffffffffu, sq, o);
    }
    __shared__ float ss[8], ssq[8];
    if ((t & 31) == 0) { ss[t >> 5] = s; ssq[t >> 5] = sq; }
    __syncthreads();
    float tot = 0.f, totq = 0.f;
    #pragma unroll
    for (int w = 0; w < 8; w++) { tot += ss[w]; totq += ssq[w]; }
    float mean = tot * (1.0f / D_);
    float var  = totq * (1.0f / D_) - mean * mean;
    out[row * D_ + t] = (v - mean) * rsqrtf(var + LN_EPS) * g[t] + beta[t];
}

// ---------------- launch ----------------------------------------------------
extern "C" void kernel_launch(void* const* d_in, const int* in_sizes, int n_in,
                              void* d_out, int out_size)
{
    const float* embed     = (const float*)d_in[0];
    // d_in[1] = refer_bbox (unused)
    const float* dist      = (const float*)d_in[2];
    const float* query_pos = (const float*)d_in[3];
    const float* in_proj_w = (const float*)d_in[4];
    const float* in_proj_b = (const float*)d_in[5];
    const float* out_w     = (const float*)d_in[6];
    const float* out_b     = (const float*)d_in[7];
    const float* tau_w     = (const float*)d_in[8];
    const float* tau_b     = (const float*)d_in[9];
    const float* w1        = (const float*)d_in[10];
    const float* b1        = (const float*)d_in[11];
    const float* w2        = (const float*)d_in[12];
    const float* b2        = (const float*)d_in[13];
    const float* g1        = (const float*)d_in[14];
    const float* beta1     = (const float*)d_in[15];
    const float* g2        = (const float*)d_in[16];
    const float* beta2     = (const float*)d_in[17];
    float* out = (float*)d_out;

    float *p_qk, *p_v, *p_tau, *p_ctx, *p_x, *p_h, *p_y;
    cudaGetSymbolAddress((void**)&p_qk,  g_qk);
    cudaGetSymbolAddress((void**)&p_v,   g_v);
    cudaGetSymbolAddress((void**)&p_tau, g_tau);
    cudaGetSymbolAddress((void**)&p_ctx, g_ctx);
    cudaGetSymbolAddress((void**)&p_x,   g_x);
    cudaGetSymbolAddress((void**)&p_h,   g_h);
    cudaGetSymbolAddress((void**)&p_y,   g_y);

    // 1. [q|k] = (embed+query_pos) @ in_proj_w[0:512].T + b  (fused add)
    mma_gemm_kernel<<<dim3(512 / GBN, ROWS / GBM), 256>>>(
        embed, query_pos, in_proj_w, in_proj_b, p_qk, ROWS, 512, D_, 0);
    // 2. v = embed @ wv.T + bv
    mma_gemm_kernel<<<dim3(D_ / GBN, ROWS / GBM), 256>>>(
        embed, nullptr, in_proj_w + 512 * D_, in_proj_b + 512, p_v, ROWS, D_, D_, 0);
    // 3. tau
    tau_kernel<<<ROWS, 256>>>(embed, tau_w, tau_b, p_tau);
    // 4. attention
    {
        int smem = (AQ * SS + AQ * GST + AJ * GST) * (int)sizeof(float);
        cudaFuncSetAttribute(attn_kernel, cudaFuncAttributeMaxDynamicSharedMemorySize, smem);
        attn_kernel<<<dim3(N_ / AQ, B_ * H_), 256, smem>>>(p_qk, p_v, p_tau, dist, p_ctx);
    }
    // 5. tgt = ctx @ out_w.T + out_b
    mma_gemm_kernel<<<dim3(D_ / GBN, ROWS / GBM), 256>>>(
        p_ctx, nullptr, out_w, out_b, p_y, ROWS, D_, D_, 0);
    // 6. x = LN1(embed + tgt)
    add_ln_kernel<<<ROWS, 256>>>(embed, p_y, g1, beta1, p_x);
    // 7. h = relu(x @ w1.T + b1)
    mma_gemm_kernel<<<dim3(FFN_ / GBN, ROWS / GBM), 256>>>(
        p_x, nullptr, w1, b1, p_h, ROWS, FFN_, D_, 1);
    // 8. y = h @ w2.T + b2
    mma_gemm_kernel<<<dim3(D_ / GBN, ROWS / GBM), 256>>>(
        p_h, nullptr, w2, b2, p_y, ROWS, D_, FFN_, 0);
    // 9. out = LN2(x + y)
    add_ln_kernel<<<ROWS, 256>>>(p_x, p_y, g2, beta2, out);
}

// round 5
// speedup vs baseline: 4.6415x; 1.7171x over previous
#include <cuda_runtime.h>
#include <math.h>
#include <stdint.h>

// Problem dims (fixed)
#define B_    4
#define N_    1024
#define D_    256
#define H_    8
#define HD_   32
#define FFN_  1024
#define ROWS  (B_*N_)          // 4096
#define LN_EPS 1e-5f

// ---------------- scratch (static device memory; no allocs) ----------------
__device__ float g_qk   [ROWS*2*D_];   // per row: [q(256) | k(256)]
__device__ float g_v    [ROWS*D_];
__device__ float g_tau  [B_*H_*N_];    // (b,h,i)
__device__ float g_ctx  [ROWS*D_];
__device__ float g_x    [ROWS*D_];     // after LN1
__device__ float g_h    [ROWS*FFN_];   // relu(ffn1)
__device__ float g_y    [ROWS*D_];     // generic GEMM output

// ---------------- helpers ---------------------------------------------------
__device__ __forceinline__ uint32_t f2tf32(float x) {
    uint32_t r;
    asm("cvt.rna.tf32.f32 %0, %1;" : "=r"(r) : "f"(x));
    return r;
}
__device__ __forceinline__ void mma8(float* c, const uint32_t* a, uint32_t b0, uint32_t b1) {
    asm volatile(
        "mma.sync.aligned.m16n8k8.row.col.f32.tf32.tf32.f32 "
        "{%0,%1,%2,%3}, {%4,%5,%6,%7}, {%8,%9}, {%0,%1,%2,%3};\n"
        : "+f"(c[0]), "+f"(c[1]), "+f"(c[2]), "+f"(c[3])
        : "r"(a[0]), "r"(a[1]), "r"(a[2]), "r"(a[3]), "r"(b0), "r"(b1));
}
__device__ __forceinline__ uint32_t smaddr(const void* p) {
    return (uint32_t)__cvta_generic_to_shared(p);
}
__device__ __forceinline__ void cp16(uint32_t dst, const void* src) {
    asm volatile("cp.async.cg.shared.global [%0], [%1], 16;\n" :: "r"(dst), "l"(src));
}
__device__ __forceinline__ void cpcommit() {
    asm volatile("cp.async.commit_group;\n" ::: "memory");
}
__device__ __forceinline__ void cpwait1() {
    asm volatile("cp.async.wait_group 1;\n" ::: "memory");
}
__device__ __forceinline__ void cpwait0() {
    asm volatile("cp.async.wait_group 0;\n" ::: "memory");
}

// ---------------- tensor-core SGEMM 64x128 (FFN1) ---------------------------
#define GBM 64
#define GBN 128
#define GBK 32
#define GST 36
__global__ __launch_bounds__(256) void mma_gemm_kernel(
    const float* __restrict__ A, const float* __restrict__ A2,
    const float* __restrict__ W, const float* __restrict__ bias,
    float* __restrict__ C, int M, int Nc, int K, int relu)
{
    __shared__ uint32_t As[GBM * GST];
    __shared__ uint32_t Ws[GBN * GST];
    const int tid = threadIdx.x;
    const int warp = tid >> 5, lane = tid & 31;
    const int grp = lane >> 2, t4 = lane & 3;
    const int wm = warp >> 2, wn = warp & 3;
    const int bm = blockIdx.y * GBM, bn = blockIdx.x * GBN;

    float acc[2][4][4] = {};
    for (int k0 = 0; k0 < K; k0 += GBK) {
        #pragma unroll
        for (int rep = 0; rep < 2; rep++) {
            int idx = tid + rep * 256;
            int r = idx >> 3, c4 = (idx & 7) * 4;
            float4 v = *(const float4*)&A[(size_t)(bm + r) * K + k0 + c4];
            if (A2) {
                float4 u = *(const float4*)&A2[(size_t)(bm + r) * K + k0 + c4];
                v.x += u.x; v.y += u.y; v.z += u.z; v.w += u.w;
            }
            As[r * GST + c4 + 0] = f2tf32(v.x);
            As[r * GST + c4 + 1] = f2tf32(v.y);
            As[r * GST + c4 + 2] = f2tf32(v.z);
            As[r * GST + c4 + 3] = f2tf32(v.w);
        }
        #pragma unroll
        for (int rep = 0; rep < 4; rep++) {
            int idx = tid + rep * 256;
            int r = idx >> 3, c4 = (idx & 7) * 4;
            float4 v = *(const float4*)&W[(size_t)(bn + r) * K + k0 + c4];
            Ws[r * GST + c4 + 0] = f2tf32(v.x);
            Ws[r * GST + c4 + 1] = f2tf32(v.y);
            Ws[r * GST + c4 + 2] = f2tf32(v.z);
            Ws[r * GST + c4 + 3] = f2tf32(v.w);
        }
        __syncthreads();
        #pragma unroll
        for (int kk = 0; kk < 4; kk++) {
            const int kb = kk * 8;
            uint32_t afr[2][4];
            #pragma unroll
            for (int mf = 0; mf < 2; mf++) {
                int rb = wm * 32 + mf * 16;
                afr[mf][0] = As[(rb + grp) * GST + kb + t4];
                afr[mf][1] = As[(rb + grp + 8) * GST + kb + t4];
                afr[mf][2] = As[(rb + grp) * GST + kb + t4 + 4];
                afr[mf][3] = As[(rb + grp + 8) * GST + kb + t4 + 4];
            }
            #pragma unroll
            for (int nf = 0; nf < 4; nf++) {
                int nrow = wn * 32 + nf * 8 + grp;
                uint32_t b0 = Ws[nrow * GST + kb + t4];
                uint32_t b1 = Ws[nrow * GST + kb + t4 + 4];
                mma8(acc[0][nf], afr[0], b0, b1);
                mma8(acc[1][nf], afr[1], b0, b1);
            }
        }
        __syncthreads();
    }
    #pragma unroll
    for (int mf = 0; mf < 2; mf++) {
        int r0 = bm + wm * 32 + mf * 16 + grp;
        #pragma unroll
        for (int nf = 0; nf < 4; nf++) {
            int c0 = bn + wn * 32 + nf * 8 + 2 * t4;
            float b0v = bias[c0], b1v = bias[c0 + 1];
            float v0 = acc[mf][nf][0] + b0v, v1 = acc[mf][nf][1] + b1v;
            float v2 = acc[mf][nf][2] + b0v, v3 = acc[mf][nf][3] + b1v;
            if (relu) {
                v0 = fmaxf(v0, 0.f); v1 = fmaxf(v1, 0.f);
                v2 = fmaxf(v2, 0.f); v3 = fmaxf(v3, 0.f);
            }
            float2 p0 = {v0, v1}, p1 = {v2, v3};
            *(float2*)&C[(size_t)r0 * Nc + c0] = p0;
            *(float2*)&C[(size_t)(r0 + 8) * Nc + c0] = p1;
        }
    }
}

// ---------------- tensor-core SGEMM 64x64 (narrow outputs) ------------------
__global__ __launch_bounds__(256) void mma_gemm64_kernel(
    const float* __restrict__ A, const float* __restrict__ A2,
    const float* __restrict__ W, const float* __restrict__ bias,
    float* __restrict__ C, int M, int Nc, int K, int relu)
{
    __shared__ uint32_t As[64 * GST];
    __shared__ uint32_t Ws[64 * GST];
    const int tid = threadIdx.x;
    const int warp = tid >> 5, lane = tid & 31;
    const int grp = lane >> 2, t4 = lane & 3;
    const int wm = warp >> 1, wn = warp & 1;      // 4 x 2 warp grid
    const int bm = blockIdx.y * 64, bn = blockIdx.x * 64;

    float acc[4][4] = {};
    for (int k0 = 0; k0 < K; k0 += GBK) {
        #pragma unroll
        for (int rep = 0; rep < 2; rep++) {
            int idx = tid + rep * 256;
            int r = idx >> 3, c4 = (idx & 7) * 4;
            float4 v = *(const float4*)&A[(size_t)(bm + r) * K + k0 + c4];
            if (A2) {
                float4 u = *(const float4*)&A2[(size_t)(bm + r) * K + k0 + c4];
                v.x += u.x; v.y += u.y; v.z += u.z; v.w += u.w;
            }
            As[r * GST + c4 + 0] = f2tf32(v.x);
            As[r * GST + c4 + 1] = f2tf32(v.y);
            As[r * GST + c4 + 2] = f2tf32(v.z);
            As[r * GST + c4 + 3] = f2tf32(v.w);
        }
        #pragma unroll
        for (int rep = 0; rep < 2; rep++) {
            int idx = tid + rep * 256;
            int r = idx >> 3, c4 = (idx & 7) * 4;
            float4 v = *(const float4*)&W[(size_t)(bn + r) * K + k0 + c4];
            Ws[r * GST + c4 + 0] = f2tf32(v.x);
            Ws[r * GST + c4 + 1] = f2tf32(v.y);
            Ws[r * GST + c4 + 2] = f2tf32(v.z);
            Ws[r * GST + c4 + 3] = f2tf32(v.w);
        }
        __syncthreads();
        #pragma unroll
        for (int kk = 0; kk < 4; kk++) {
            const int kb = kk * 8;
            uint32_t a[4];
            int rb = wm * 16;
            a[0] = As[(rb + grp) * GST + kb + t4];
            a[1] = As[(rb + grp + 8) * GST + kb + t4];
            a[2] = As[(rb + grp) * GST + kb + t4 + 4];
            a[3] = As[(rb + grp + 8) * GST + kb + t4 + 4];
            #pragma unroll
            for (int nf = 0; nf < 4; nf++) {
                int nrow = wn * 32 + nf * 8 + grp;
                uint32_t b0 = Ws[nrow * GST + kb + t4];
                uint32_t b1 = Ws[nrow * GST + kb + t4 + 4];
                mma8(acc[nf], a, b0, b1);
            }
        }
        __syncthreads();
    }
    int r0 = bm + wm * 16 + grp;
    #pragma unroll
    for (int nf = 0; nf < 4; nf++) {
        int c0 = bn + wn * 32 + nf * 8 + 2 * t4;
        float b0v = bias[c0], b1v = bias[c0 + 1];
        float v0 = acc[nf][0] + b0v, v1 = acc[nf][1] + b1v;
        float v2 = acc[nf][2] + b0v, v3 = acc[nf][3] + b1v;
        if (relu) {
            v0 = fmaxf(v0, 0.f); v1 = fmaxf(v1, 0.f);
            v2 = fmaxf(v2, 0.f); v3 = fmaxf(v3, 0.f);
        }
        float2 p0 = {v0, v1}, p1 = {v2, v3};
        *(float2*)&C[(size_t)r0 * Nc + c0] = p0;
        *(float2*)&C[(size_t)(r0 + 8) * Nc + c0] = p1;
    }
}

// ---------------- tau: warp per row, all 8 heads -----------------------------
__global__ __launch_bounds__(256) void tau_kernel(
    const float* __restrict__ embed, const float* __restrict__ tw,
    const float* __restrict__ tb, float* __restrict__ tau)
{
    __shared__ float ws[H_ * D_];
    for (int i = threadIdx.x; i < H_ * D_; i += 256) ws[i] = tw[i];
    __syncthreads();
    const int warp = threadIdx.x >> 5, lane = threadIdx.x & 31;
    const int row = blockIdx.x * 8 + warp;
    const int b = row >> 10, i = row & 1023;
    float e[8];
    #pragma unroll
    for (int k = 0; k < 8; k++) e[k] = embed[(size_t)row * D_ + k * 32 + lane];
    #pragma unroll
    for (int h = 0; h < H_; h++) {
        float s = 0.f;
        #pragma unroll
        for (int k = 0; k < 8; k++) s += e[k] * ws[h * D_ + k * 32 + lane];
        #pragma unroll
        for (int o = 16; o; o >>= 1) s += __shfl_xor_sync(0xffffffffu, s, o);
        if (lane == 0) tau[(b * H_ + h) * N_ + i] = s + tb[h];
    }
}

// ---------------- flash attention (online softmax, cp.async pipeline) -------
#define BQ 128
#define JT 64
#define PST 68
#define KST 36
#define NTILES (N_/JT)
__global__ __launch_bounds__(256, 2) void flash_attn_kernel(
    const float* __restrict__ qk, const float* __restrict__ vbuf,
    const float* __restrict__ tau, const float* __restrict__ dist,
    float* __restrict__ ctx)
{
    extern __shared__ float sm[];
    float* Ps = sm;                       // [128][68]  Q staging, then P tiles
    float* Ks = Ps + BQ * PST;            // [2][64][36]
    float* Vs = Ks + 2 * JT * KST;        // [2][64][36]

    const int bh = blockIdx.y;
    const int b = bh >> 3, h = bh & 7;
    const int i0 = blockIdx.x * BQ;
    const int tid = threadIdx.x;
    const int warp = tid >> 5, lane = tid & 31;
    const int grp = lane >> 2, t4 = lane & 3;
    const int row_a = warp * 16 + grp, row_b = row_a + 8;

    // prefetch KV tile 0
    {
        #pragma unroll
        for (int rep = 0; rep < 2; rep++) {
            int idx = tid + rep * 256;
            int r = idx >> 3, c4 = (idx & 7) * 4;
            cp16(smaddr(&Ks[r * KST + c4]),
                 &qk[(size_t)(b * N_ + r) * (2 * D_) + D_ + h * HD_ + c4]);
            cp16(smaddr(&Vs[r * KST + c4]),
                 &vbuf[(size_t)(b * N_ + r) * D_ + h * HD_ + c4]);
        }
        cpcommit();
    }

    // stage Q (coalesced), then grab A-frags (rounded to tf32)
    #pragma unroll
    for (int rep = 0; rep < 4; rep++) {
        int idx = tid + rep * 256;
        int r = idx >> 3, c4 = (idx & 7) * 4;
        float4 v = *(const float4*)&qk[(size_t)(b * N_ + i0 + r) * (2 * D_) + h * HD_ + c4];
        *(float4*)&Ps[r * PST + c4] = v;
    }
    __syncthreads();
    uint32_t q[4][4];
    {
        const uint32_t* Pu = (const uint32_t*)Ps;
        #pragma unroll
        for (int s = 0; s < 4; s++) {
            q[s][0] = f2tf32(__uint_as_float(Pu[row_a * PST + 8 * s + t4]));
            q[s][1] = f2tf32(__uint_as_float(Pu[row_b * PST + 8 * s + t4]));
            q[s][2] = f2tf32(__uint_as_float(Pu[row_a * PST + 8 * s + t4 + 4]));
            q[s][3] = f2tf32(__uint_as_float(Pu[row_b * PST + 8 * s + t4 + 4]));
        }
    }

    const float tau_a = tau[(b * H_ + h) * N_ + i0 + row_a];
    const float tau_b = tau[(b * H_ + h) * N_ + i0 + row_b];
    const float scale = 0.17677669529663688f;   // 1/sqrt(32)
    float m_a = -1e30f, m_b = -1e30f, l_a = 0.f, l_b = 0.f;
    float O[4][4] = {};

    for (int t = 0; t < NTILES; t++) {
        const int buf = t & 1;
        if (t + 1 < NTILES) {
            const int nb = buf ^ 1;
            #pragma unroll
            for (int rep = 0; rep < 2; rep++) {
                int idx = tid + rep * 256;
                int r = idx >> 3, c4 = (idx & 7) * 4;
                cp16(smaddr(&Ks[nb * JT * KST + r * KST + c4]),
                     &qk[(size_t)(b * N_ + (t + 1) * JT + r) * (2 * D_) + D_ + h * HD_ + c4]);
                cp16(smaddr(&Vs[nb * JT * KST + r * KST + c4]),
                     &vbuf[(size_t)(b * N_ + (t + 1) * JT + r) * D_ + h * HD_ + c4]);
            }
            cpcommit();
            cpwait1();
        } else {
            cpwait0();
        }
        __syncthreads();

        // dist tile -> regs (overlaps with QK mma)
        float2 da[8], db[8];
        {
            const float* dr_a = &dist[(size_t)(b * N_ + i0 + row_a) * N_ + t * JT];
            const float* dr_b = &dist[(size_t)(b * N_ + i0 + row_b) * N_ + t * JT];
            #pragma unroll
            for (int nf = 0; nf < 8; nf++) {
                da[nf] = *(const float2*)&dr_a[nf * 8 + 2 * t4];
                db[nf] = *(const float2*)&dr_b[nf * 8 + 2 * t4];
            }
        }

        // QK: 16x64 scores per warp
        float acc[8][4] = {};
        {
            const uint32_t* Ku = (const uint32_t*)&Ks[buf * JT * KST];
            #pragma unroll
            for (int s = 0; s < 4; s++) {
                #pragma unroll
                for (int nf = 0; nf < 8; nf++) {
                    uint32_t b0 = Ku[(nf * 8 + grp) * KST + 8 * s + t4];
                    uint32_t b1 = Ku[(nf * 8 + grp) * KST + 8 * s + t4 + 4];
                    mma8(acc[nf], q[s], b0, b1);
                }
            }
        }

        // bias + tile max
        float mn_a = -1e30f, mn_b = -1e30f;
        #pragma unroll
        for (int nf = 0; nf < 8; nf++) {
            acc[nf][0] = acc[nf][0] * scale + da[nf].x * tau_a;
            acc[nf][1] = acc[nf][1] * scale + da[nf].y * tau_a;
            acc[nf][2] = acc[nf][2] * scale + db[nf].x * tau_b;
            acc[nf][3] = acc[nf][3] * scale + db[nf].y * tau_b;
            mn_a = fmaxf(mn_a, fmaxf(acc[nf][0], acc[nf][1]));
            mn_b = fmaxf(mn_b, fmaxf(acc[nf][2], acc[nf][3]));
        }
        mn_a = fmaxf(mn_a, __shfl_xor_sync(0xffffffffu, mn_a, 1));
        mn_a = fmaxf(mn_a, __shfl_xor_sync(0xffffffffu, mn_a, 2));
        mn_b = fmaxf(mn_b, __shfl_xor_sync(0xffffffffu, mn_b, 1));
        mn_b = fmaxf(mn_b, __shfl_xor_sync(0xffffffffu, mn_b, 2));

        const float mx_a = fmaxf(m_a, mn_a), mx_b = fmaxf(m_b, mn_b);
        const float al_a = __expf(m_a - mx_a), al_b = __expf(m_b - mx_b);
        m_a = mx_a; m_b = mx_b;

        // exp (rounded to tf32 so P@V numerator matches l denominator)
        float sum_a = 0.f, sum_b = 0.f;
        #pragma unroll
        for (int nf = 0; nf < 8; nf++) {
            acc[nf][0] = __uint_as_float(f2tf32(__expf(acc[nf][0] - mx_a)));
            acc[nf][1] = __uint_as_float(f2tf32(__expf(acc[nf][1] - mx_a)));
            acc[nf][2] = __uint_as_float(f2tf32(__expf(acc[nf][2] - mx_b)));
            acc[nf][3] = __uint_as_float(f2tf32(__expf(acc[nf][3] - mx_b)));
            sum_a += acc[nf][0] + acc[nf][1];
            sum_b += acc[nf][2] + acc[nf][3];
        }
        sum_a += __shfl_xor_sync(0xffffffffu, sum_a, 1);
        sum_a += __shfl_xor_sync(0xffffffffu, sum_a, 2);
        sum_b += __shfl_xor_sync(0xffffffffu, sum_b, 1);
        sum_b += __shfl_xor_sync(0xffffffffu, sum_b, 2);
        l_a = l_a * al_a + sum_a;
        l_b = l_b * al_b + sum_b;

        // rescale O
        #pragma unroll
        for (int nf = 0; nf < 4; nf++) {
            O[nf][0] *= al_a; O[nf][1] *= al_a;
            O[nf][2] *= al_b; O[nf][3] *= al_b;
        }

        // store P tile (warp-private rows), then PV mma
        #pragma unroll
        for (int nf = 0; nf < 8; nf++) {
            float2 p0 = {acc[nf][0], acc[nf][1]};
            float2 p1 = {acc[nf][2], acc[nf][3]};
            *(float2*)&Ps[row_a * PST + nf * 8 + 2 * t4] = p0;
            *(float2*)&Ps[row_b * PST + nf * 8 + 2 * t4] = p1;
        }
        __syncwarp();
        {
            const uint32_t* Pu = (const uint32_t*)Ps;
            const uint32_t* Vu = (const uint32_t*)&Vs[buf * JT * KST];
            #pragma unroll
            for (int ks = 0; ks < 8; ks++) {
                uint32_t a[4];
                a[0] = Pu[row_a * PST + ks * 8 + t4];
                a[1] = Pu[row_b * PST + ks * 8 + t4];
                a[2] = Pu[row_a * PST + ks * 8 + t4 + 4];
                a[3] = Pu[row_b * PST + ks * 8 + t4 + 4];
                #pragma unroll
                for (int nf = 0; nf < 4; nf++) {
                    uint32_t b0 = Vu[(ks * 8 + t4) * KST + nf * 8 + grp];
                    uint32_t b1 = Vu[(ks * 8 + t4 + 4) * KST + nf * 8 + grp];
                    mma8(O[nf], a, b0, b1);
                }
            }
        }
        __syncthreads();
    }

    // epilogue: normalize and write
    const float ia = 1.0f / l_a, ib = 1.0f / l_b;
    #pragma unroll
    for (int nf = 0; nf < 4; nf++) {
        float2 p0 = {O[nf][0] * ia, O[nf][1] * ia};
        float2 p1 = {O[nf][2] * ib, O[nf][3] * ib};
        *(float2*)&ctx[(size_t)(b * N_ + i0 + row_a) * D_ + h * HD_ + nf * 8 + 2 * t4] = p0;
        *(float2*)&ctx[(size_t)(b * N_ + i0 + row_b) * D_ + h * HD_ + nf * 8 + 2 * t4] = p1;
    }
}

// ---------------- fused add + layernorm ------------------------------------
__global__ __launch_bounds__(256) void add_ln_kernel(
    const float* __restrict__ A, const float* __restrict__ Bv,
    const float* __restrict__ g, const float* __restrict__ beta,
    float* __restrict__ out)
{
    const int row = blockIdx.x;
    const int t = threadIdx.x;
    float v = A[row * D_ + t] + Bv[row * D_ + t];
    float s = v, sq = v * v;
    #pragma unroll
    for (int o = 16; o; o >>= 1) {
        s  += __shfl_xor_sync(0xffffffffu, s,  o);
        sq += __shfl_xor_sync(0xffffffffu, sq, o);
    }
    __shared__ float ss[8], ssq[8];
    if ((t & 31) == 0) { ss[t >> 5] = s; ssq[t >> 5] = sq; }
    __syncthreads();
    float tot = 0.f, totq = 0.f;
    #pragma unroll
    for (int w = 0; w < 8; w++) { tot += ss[w]; totq += ssq[w]; }
    float mean = tot * (1.0f / D_);
    float var  = totq * (1.0f / D_) - mean * mean;
    out[row * D_ + t] = (v - mean) * rsqrtf(var + LN_EPS) * g[t] + beta[t];
}

// ---------------- launch ----------------------------------------------------
extern "C" void kernel_launch(void* const* d_in, const int* in_sizes, int n_in,
                              void* d_out, int out_size)
{
    const float* embed     = (const float*)d_in[0];
    // d_in[1] = refer_bbox (unused)
    const float* dist      = (const float*)d_in[2];
    const float* query_pos = (const float*)d_in[3];
    const float* in_proj_w = (const float*)d_in[4];
    const float* in_proj_b = (const float*)d_in[5];
    const float* out_w     = (const float*)d_in[6];
    const float* out_b     = (const float*)d_in[7];
    const float* tau_w     = (const float*)d_in[8];
    const float* tau_b     = (const float*)d_in[9];
    const float* w1        = (const float*)d_in[10];
    const float* b1        = (const float*)d_in[11];
    const float* w2        = (const float*)d_in[12];
    const float* b2        = (const float*)d_in[13];
    const float* g1        = (const float*)d_in[14];
    const float* beta1     = (const float*)d_in[15];
    const float* g2        = (const float*)d_in[16];
    const float* beta2     = (const float*)d_in[17];
    float* out = (float*)d_out;

    float *p_qk, *p_v, *p_tau, *p_ctx, *p_x, *p_h, *p_y;
    cudaGetSymbolAddress((void**)&p_qk,  g_qk);
    cudaGetSymbolAddress((void**)&p_v,   g_v);
    cudaGetSymbolAddress((void**)&p_tau, g_tau);
    cudaGetSymbolAddress((void**)&p_ctx, g_ctx);
    cudaGetSymbolAddress((void**)&p_x,   g_x);
    cudaGetSymbolAddress((void**)&p_h,   g_h);
    cudaGetSymbolAddress((void**)&p_y,   g_y);

    // 1. [q|k] = (embed+query_pos) @ in_proj_w[0:512].T + b  (fused add)
    mma_gemm64_kernel<<<dim3(512 / 64, ROWS / 64), 256>>>(
        embed, query_pos, in_proj_w, in_proj_b, p_qk, ROWS, 512, D_, 0);
    // 2. v = embed @ wv.T + bv
    mma_gemm64_kernel<<<dim3(D_ / 64, ROWS / 64), 256>>>(
        embed, nullptr, in_proj_w + 512 * D_, in_proj_b + 512, p_v, ROWS, D_, D_, 0);
    // 3. tau
    tau_kernel<<<ROWS / 8, 256>>>(embed, tau_w, tau_b, p_tau);
    // 4. flash attention
    {
        int smem = (BQ * PST + 4 * JT * KST) * (int)sizeof(float);  // 71680 B
        cudaFuncSetAttribute(flash_attn_kernel, cudaFuncAttributeMaxDynamicSharedMemorySize, smem);
        flash_attn_kernel<<<dim3(N_ / BQ, B_ * H_), 256, smem>>>(p_qk, p_v, p_tau, dist, p_ctx);
    }
    // 5. tgt = ctx @ out_w.T + out_b
    mma_gemm64_kernel<<<dim3(D_ / 64, ROWS / 64), 256>>>(
        p_ctx, nullptr, out_w, out_b, p_y, ROWS, D_, D_, 0);
    // 6. x = LN1(embed + tgt)
    add_ln_kernel<<<ROWS, 256>>>(embed, p_y, g1, beta1, p_x);
    // 7. h = relu(x @ w1.T + b1)
    mma_gemm_kernel<<<dim3(FFN_ / GBN, ROWS / GBM), 256>>>(
        p_x, nullptr, w1, b1, p_h, ROWS, FFN_, D_, 1);
    // 8. y = h @ w2.T + b2
    mma_gemm64_kernel<<<dim3(D_ / 64, ROWS / 64), 256>>>(
        p_h, nullptr, w2, b2, p_y, ROWS, D_, FFN_, 0);
    // 9. out = LN2(x + y)
    add_ln_kernel<<<ROWS, 256>>>(p_x, p_y, g2, beta2, out);
}

// round 7
// speedup vs baseline: 6.4988x; 1.4001x over previous
#include <cuda_runtime.h>
#include <cuda_fp16.h>
#include <math.h>
#include <stdint.h>

// Problem dims (fixed)
#define B_    4
#define N_    1024
#define D_    256
#define H_    8
#define HD_   32
#define FFN_  1024
#define ROWS  (B_*N_)          // 4096
#define LN_EPS 1e-5f

// ---------------- scratch (static device memory; no allocs) ----------------
__device__ float  g_qksum[ROWS*D_];                    // embed + query_pos
__device__ __align__(16) __half g_qk_h[ROWS*2*D_];     // per row: [q(256)|k(256)] fp16
__device__ __align__(16) __half g_v_h [ROWS*D_];       // v fp16
__device__ float  g_tau[B_*H_*N_];
__device__ float  g_ctx[ROWS*D_];
__device__ float  g_x  [ROWS*D_];
__device__ float  g_h  [ROWS*FFN_];
__device__ float  g_y  [ROWS*D_];

// ---------------- helpers ---------------------------------------------------
__device__ __forceinline__ void mma8(float* c, const uint32_t* a, uint32_t b0, uint32_t b1) {
    asm volatile(
        "mma.sync.aligned.m16n8k8.row.col.f32.tf32.tf32.f32 "
        "{%0,%1,%2,%3}, {%4,%5,%6,%7}, {%8,%9}, {%0,%1,%2,%3};\n"
        : "+f"(c[0]), "+f"(c[1]), "+f"(c[2]), "+f"(c[3])
        : "r"(a[0]), "r"(a[1]), "r"(a[2]), "r"(a[3]), "r"(b0), "r"(b1));
}
__device__ __forceinline__ void mma16(float* c, const uint32_t* a, uint32_t b0, uint32_t b1) {
    asm volatile(
        "mma.sync.aligned.m16n8k16.row.col.f32.f16.f16.f32 "
        "{%0,%1,%2,%3}, {%4,%5,%6,%7}, {%8,%9}, {%0,%1,%2,%3};\n"
        : "+f"(c[0]), "+f"(c[1]), "+f"(c[2]), "+f"(c[3])
        : "r"(a[0]), "r"(a[1]), "r"(a[2]), "r"(a[3]), "r"(b0), "r"(b1));
}
__device__ __forceinline__ void ldsm4(uint32_t* r, uint32_t addr) {
    asm volatile("ldmatrix.sync.aligned.m8n8.x4.shared.b16 {%0,%1,%2,%3}, [%4];"
        : "=r"(r[0]), "=r"(r[1]), "=r"(r[2]), "=r"(r[3]) : "r"(addr));
}
__device__ __forceinline__ void ldsm4t(uint32_t* r, uint32_t addr) {
    asm volatile("ldmatrix.sync.aligned.m8n8.x4.trans.shared.b16 {%0,%1,%2,%3}, [%4];"
        : "=r"(r[0]), "=r"(r[1]), "=r"(r[2]), "=r"(r[3]) : "r"(addr));
}
__device__ __forceinline__ uint32_t packh2(float lo, float hi) {
    __half2 p = __floats2half2_rn(lo, hi);
    return *reinterpret_cast<uint32_t*>(&p);
}
__device__ __forceinline__ uint32_t smaddr(const void* p) {
    return (uint32_t)__cvta_generic_to_shared(p);
}
__device__ __forceinline__ void cp16(uint32_t dst, const void* src) {
    asm volatile("cp.async.cg.shared.global [%0], [%1], 16;\n" :: "r"(dst), "l"(src));
}
__device__ __forceinline__ void cpcommit() { asm volatile("cp.async.commit_group;\n" ::: "memory"); }
__device__ __forceinline__ void cpwait1()  { asm volatile("cp.async.wait_group 1;\n" ::: "memory"); }
__device__ __forceinline__ void cpwait0()  { asm volatile("cp.async.wait_group 0;\n" ::: "memory"); }

// ---------------- addvec: qksum = embed + query_pos -------------------------
__global__ void addvec_kernel(const float* __restrict__ a, const float* __restrict__ b,
                              float* __restrict__ c, int n4) {
    int i = blockIdx.x * blockDim.x + threadIdx.x;
    if (i < n4) {
        float4 av = ((const float4*)a)[i];
        float4 bv = ((const float4*)b)[i];
        float4 cv = {av.x+bv.x, av.y+bv.y, av.z+bv.z, av.w+bv.w};
        ((float4*)c)[i] = cv;
    }
}

// ---------------- pipelined tf32 GEMM: C = act(A @ W^T + bias) --------------
// BM=128, BN=64, BK=32, 256 threads, double-buffered cp.async (raw fp32 -> tf32 trunc)
#define PST 36
__global__ __launch_bounds__(256) void pgemm_kernel(
    const float* __restrict__ A, const float* __restrict__ W,
    const float* __restrict__ bias, void* __restrict__ Cv,
    int M, int Nc, int K, int relu, int half_out)
{
    extern __shared__ uint32_t ps[];
    uint32_t* As = ps;                 // [2][128*36]
    uint32_t* Ws = ps + 2 * 128 * PST; // [2][64*36]
    const int tid = threadIdx.x;
    const int warp = tid >> 5, lane = tid & 31;
    const int grp = lane >> 2, t4 = lane & 3;
    const int wm = warp >> 1, wn = warp & 1;      // 4x2 warps; warp tile 32x32
    const int bm = blockIdx.y * 128, bn = blockIdx.x * 64;
    const int KT = K >> 5;

    // prefetch tile 0
    {
        #pragma unroll
        for (int rep = 0; rep < 4; rep++) {
            int idx = tid + rep * 256;
            int r = idx >> 3, c4 = (idx & 7) * 4;
            cp16(smaddr(&As[r * PST + c4]), &A[(size_t)(bm + r) * K + c4]);
        }
        #pragma unroll
        for (int rep = 0; rep < 2; rep++) {
            int idx = tid + rep * 256;
            int r = idx >> 3, c4 = (idx & 7) * 4;
            cp16(smaddr(&Ws[r * PST + c4]), &W[(size_t)(bn + r) * K + c4]);
        }
        cpcommit();
    }

    float acc[2][4][4] = {};
    for (int kt = 0; kt < KT; kt++) {
        const int buf = kt & 1;
        if (kt + 1 < KT) {
            const int nb = buf ^ 1;
            const int k0 = (kt + 1) * 32;
            #pragma unroll
            for (int rep = 0; rep < 4; rep++) {
                int idx = tid + rep * 256;
                int r = idx >> 3, c4 = (idx & 7) * 4;
                cp16(smaddr(&As[nb * 128 * PST + r * PST + c4]), &A[(size_t)(bm + r) * K + k0 + c4]);
            }
            #pragma unroll
            for (int rep = 0; rep < 2; rep++) {
                int idx = tid + rep * 256;
                int r = idx >> 3, c4 = (idx & 7) * 4;
                cp16(smaddr(&Ws[nb * 64 * PST + r * PST + c4]), &W[(size_t)(bn + r) * K + k0 + c4]);
            }
            cpcommit();
            cpwait1();
        } else {
            cpwait0();
        }
        __syncthreads();

        const uint32_t* Ab = &As[buf * 128 * PST];
        const uint32_t* Wb = &Ws[buf * 64 * PST];
        #pragma unroll
        for (int kk = 0; kk < 4; kk++) {
            const int kb = kk * 8;
            uint32_t afr[2][4];
            #pragma unroll
            for (int mf = 0; mf < 2; mf++) {
                int rb = wm * 32 + mf * 16;
                afr[mf][0] = Ab[(rb + grp) * PST + kb + t4];
                afr[mf][1] = Ab[(rb + grp + 8) * PST + kb + t4];
                afr[mf][2] = Ab[(rb + grp) * PST + kb + t4 + 4];
                afr[mf][3] = Ab[(rb + grp + 8) * PST + kb + t4 + 4];
            }
            #pragma unroll
            for (int nf = 0; nf < 4; nf++) {
                int nrow = wn * 32 + nf * 8 + grp;
                uint32_t b0 = Wb[nrow * PST + kb + t4];
                uint32_t b1 = Wb[nrow * PST + kb + t4 + 4];
                mma8(acc[0][nf], afr[0], b0, b1);
                mma8(acc[1][nf], afr[1], b0, b1);
            }
        }
        __syncthreads();
    }

    #pragma unroll
    for (int mf = 0; mf < 2; mf++) {
        int r0 = bm + wm * 32 + mf * 16 + grp;
        #pragma unroll
        for (int nf = 0; nf < 4; nf++) {
            int c0 = bn + wn * 32 + nf * 8 + 2 * t4;
            float b0v = bias[c0], b1v = bias[c0 + 1];
            float v0 = acc[mf][nf][0] + b0v, v1 = acc[mf][nf][1] + b1v;
            float v2 = acc[mf][nf][2] + b0v, v3 = acc[mf][nf][3] + b1v;
            if (relu) {
                v0 = fmaxf(v0, 0.f); v1 = fmaxf(v1, 0.f);
                v2 = fmaxf(v2, 0.f); v3 = fmaxf(v3, 0.f);
            }
            if (half_out) {
                __half* Ch = (__half*)Cv;
                *(__half2*)&Ch[(size_t)r0 * Nc + c0]       = __floats2half2_rn(v0, v1);
                *(__half2*)&Ch[(size_t)(r0 + 8) * Nc + c0] = __floats2half2_rn(v2, v3);
            } else {
                float* C = (float*)Cv;
                float2 p0 = {v0, v1}, p1 = {v2, v3};
                *(float2*)&C[(size_t)r0 * Nc + c0] = p0;
                *(float2*)&C[(size_t)(r0 + 8) * Nc + c0] = p1;
            }
        }
    }
}

// ---------------- tau: warp per row, all 8 heads -----------------------------
__global__ __launch_bounds__(256) void tau_kernel(
    const float* __restrict__ embed, const float* __restrict__ tw,
    const float* __restrict__ tb, float* __restrict__ tau)
{
    __shared__ float ws[H_ * D_];
    for (int i = threadIdx.x; i < H_ * D_; i += 256) ws[i] = tw[i];
    __syncthreads();
    const int warp = threadIdx.x >> 5, lane = threadIdx.x & 31;
    const int row = blockIdx.x * 8 + warp;
    const int b = row >> 10, i = row & 1023;
    float e[8];
    #pragma unroll
    for (int k = 0; k < 8; k++) e[k] = embed[(size_t)row * D_ + k * 32 + lane];
    #pragma unroll
    for (int h = 0; h < H_; h++) {
        float s = 0.f;
        #pragma unroll
        for (int k = 0; k < 8; k++) s += e[k] * ws[h * D_ + k * 32 + lane];
        #pragma unroll
        for (int o = 16; o; o >>= 1) s += __shfl_xor_sync(0xffffffffu, s, o);
        if (lane == 0) tau[(b * H_ + h) * N_ + i] = s + tb[h];
    }
}

// ---------------- fp16 flash attention (ldmatrix + register P reuse) --------
#define BQ 128
#define JT 64
#define HSTR 40          // half row stride (32 + 8 pad) -> conflict-free ldsm
#define NTILES (N_/JT)
__global__ __launch_bounds__(256, 2) void flash_attn_kernel(
    const __half* __restrict__ qh, const __half* __restrict__ vh,
    const float* __restrict__ tau, const float* __restrict__ dist,
    float* __restrict__ ctx)
{
    __shared__ __half Qs[BQ * HSTR];
    __shared__ __half Ks[2][JT * HSTR];
    __shared__ __half Vs[2][JT * HSTR];

    const int bh = blockIdx.y;
    const int b = bh >> 3, h = bh & 7;
    const int i0 = blockIdx.x * BQ;
    const int tid = threadIdx.x;
    const int warp = tid >> 5, lane = tid & 31;
    const int grp = lane >> 2, t4 = lane & 3;
    const int wb = warp * 16;
    const int row_a = wb + grp, row_b = row_a + 8;

    // ldmatrix lane address components
    const int r8a = ((lane >> 3) & 1) * 8 + (lane & 7);   // Q (rows), V (keys)
    const int c8a = ((lane >> 4) & 1) * 8;                // Q (cols),  V (dims)
    const int r8b = ((lane >> 4) & 1) * 8 + (lane & 7);   // K (keys)
    const int c8b = ((lane >> 3) & 1) * 8;                // K (cols)

    // stage Q + K/V tile 0 (one cp.async group)
    {
        #pragma unroll
        for (int rep = 0; rep < 2; rep++) {
            int idx = tid + rep * 256;
            int r = idx >> 2, seg = idx & 3;
            cp16(smaddr(&Qs[r * HSTR + seg * 8]),
                 &qh[(size_t)(b * N_ + i0 + r) * (2 * D_) + h * HD_ + seg * 8]);
        }
        int r = tid >> 2, seg = tid & 3;
        cp16(smaddr(&Ks[0][r * HSTR + seg * 8]),
             &qh[(size_t)(b * N_ + r) * (2 * D_) + D_ + h * HD_ + seg * 8]);
        cp16(smaddr(&Vs[0][r * HSTR + seg * 8]),
             &vh[(size_t)(b * N_ + r) * D_ + h * HD_ + seg * 8]);
        cpcommit();
    }

    const float tau_a = tau[(b * H_ + h) * N_ + i0 + row_a];
    const float tau_b = tau[(b * H_ + h) * N_ + i0 + row_b];
    const float scale = 0.17677669529663688f;   // 1/sqrt(32)
    float m_a = -1e30f, m_b = -1e30f, l_a = 0.f, l_b = 0.f;
    float O[4][4] = {};
    uint32_t qa[2][4];

    for (int t = 0; t < NTILES; t++) {
        const int buf = t & 1;
        if (t + 1 < NTILES) {
            const int nb = buf ^ 1;
            int r = tid >> 2, seg = tid & 3;
            int j1 = (t + 1) * JT;
            cp16(smaddr(&Ks[nb][r * HSTR + seg * 8]),
                 &qh[(size_t)(b * N_ + j1 + r) * (2 * D_) + D_ + h * HD_ + seg * 8]);
            cp16(smaddr(&Vs[nb][r * HSTR + seg * 8]),
                 &vh[(size_t)(b * N_ + j1 + r) * D_ + h * HD_ + seg * 8]);
            cpcommit();
            cpwait1();
        } else {
            cpwait0();
        }
        __syncthreads();

        if (t == 0) {
            #pragma unroll
            for (int s = 0; s < 2; s++)
                ldsm4(qa[s], smaddr(&Qs[(wb + r8a) * HSTR + s * 16 + c8a]));
        }

        // ---- QK: 16x64 scores per warp ----
        float acc[8][4] = {};
        #pragma unroll
        for (int s = 0; s < 2; s++) {
            #pragma unroll
            for (int nf2 = 0; nf2 < 4; nf2++) {
                uint32_t kb4[4];
                ldsm4(kb4, smaddr(&Ks[buf][(nf2 * 16 + r8b) * HSTR + s * 16 + c8b]));
                mma16(acc[2 * nf2],     qa[s], kb4[0], kb4[1]);
                mma16(acc[2 * nf2 + 1], qa[s], kb4[2], kb4[3]);
            }
        }

        // ---- bias + tile max ----
        const int j0 = t * JT;
        float mn_a = -1e30f, mn_b = -1e30f;
        #pragma unroll
        for (int nf = 0; nf < 8; nf++) {
            float2 da = *(const float2*)&dist[(size_t)(b * N_ + i0 + row_a) * N_ + j0 + nf * 8 + 2 * t4];
            float2 db = *(const float2*)&dist[(size_t)(b * N_ + i0 + row_b) * N_ + j0 + nf * 8 + 2 * t4];
            acc[nf][0] = acc[nf][0] * scale + da.x * tau_a;
            acc[nf][1] = acc[nf][1] * scale + da.y * tau_a;
            acc[nf][2] = acc[nf][2] * scale + db.x * tau_b;
            acc[nf][3] = acc[nf][3] * scale + db.y * tau_b;
            mn_a = fmaxf(mn_a, fmaxf(acc[nf][0], acc[nf][1]));
            mn_b = fmaxf(mn_b, fmaxf(acc[nf][2], acc[nf][3]));
        }
        mn_a = fmaxf(mn_a, __shfl_xor_sync(0xffffffffu, mn_a, 1));
        mn_a = fmaxf(mn_a, __shfl_xor_sync(0xffffffffu, mn_a, 2));
        mn_b = fmaxf(mn_b, __shfl_xor_sync(0xffffffffu, mn_b, 1));
        mn_b = fmaxf(mn_b, __shfl_xor_sync(0xffffffffu, mn_b, 2));

        const float mx_a = fmaxf(m_a, mn_a), mx_b = fmaxf(m_b, mn_b);
        const float al_a = __expf(m_a - mx_a), al_b = __expf(m_b - mx_b);
        m_a = mx_a; m_b = mx_b;

        float sum_a = 0.f, sum_b = 0.f;
        #pragma unroll
        for (int nf = 0; nf < 8; nf++) {
            acc[nf][0] = __expf(acc[nf][0] - mx_a);
            acc[nf][1] = __expf(acc[nf][1] - mx_a);
            acc[nf][2] = __expf(acc[nf][2] - mx_b);
            acc[nf][3] = __expf(acc[nf][3] - mx_b);
            sum_a += acc[nf][0] + acc[nf][1];
            sum_b += acc[nf][2] + acc[nf][3];
        }
        sum_a += __shfl_xor_sync(0xffffffffu, sum_a, 1);
        sum_a += __shfl_xor_sync(0xffffffffu, sum_a, 2);
        sum_b += __shfl_xor_sync(0xffffffffu, sum_b, 1);
        sum_b += __shfl_xor_sync(0xffffffffu, sum_b, 2);
        l_a = l_a * al_a + sum_a;
        l_b = l_b * al_b + sum_b;

        #pragma unroll
        for (int nf = 0; nf < 4; nf++) {
            O[nf][0] *= al_a; O[nf][1] *= al_a;
            O[nf][2] *= al_b; O[nf][3] *= al_b;
        }

        // ---- PV: P comes straight from accumulators (packed to fp16) ----
        #pragma unroll
        for (int ks = 0; ks < 4; ks++) {
            uint32_t a[4];
            a[0] = packh2(acc[2 * ks][0],     acc[2 * ks][1]);
            a[1] = packh2(acc[2 * ks][2],     acc[2 * ks][3]);
            a[2] = packh2(acc[2 * ks + 1][0], acc[2 * ks + 1][1]);
            a[3] = packh2(acc[2 * ks + 1][2], acc[2 * ks + 1][3]);
            #pragma unroll
            for (int nfp = 0; nfp < 2; nfp++) {
                uint32_t vb4[4];
                ldsm4t(vb4, smaddr(&Vs[buf][(ks * 16 + r8a) * HSTR + nfp * 16 + c8a]));
                mma16(O[2 * nfp],     a, vb4[0], vb4[1]);
                mma16(O[2 * nfp + 1], a, vb4[2], vb4[3]);
            }
        }
        __syncthreads();
    }

    // epilogue: normalize, write fp32 ctx
    const float ia = 1.0f / l_a, ib = 1.0f / l_b;
    #pragma unroll
    for (int nf = 0; nf < 4; nf++) {
        float2 p0 = {O[nf][0] * ia, O[nf][1] * ia};
        float2 p1 = {O[nf][2] * ib, O[nf][3] * ib};
        *(float2*)&ctx[(size_t)(b * N_ + i0 + row_a) * D_ + h * HD_ + nf * 8 + 2 * t4] = p0;
        *(float2*)&ctx[(size_t)(b * N_ + i0 + row_b) * D_ + h * HD_ + nf * 8 + 2 * t4] = p1;
    }
}

// ---------------- fused add + layernorm ------------------------------------
__global__ __launch_bounds__(256) void add_ln_kernel(
    const float* __restrict__ A, const float* __restrict__ Bv,
    const float* __restrict__ g, const float* __restrict__ beta,
    float* __restrict__ out)
{
    const int row = blockIdx.x;
    const int t = threadIdx.x;
    float v = A[row * D_ + t] + Bv[row * D_ + t];
    float s = v, sq = v * v;
    #pragma unroll
    for (int o = 16; o; o >>= 1) {
        s  += __shfl_xor_sync(0xffffffffu, s,  o);
        sq += __shfl_xor_sync(0xffffffffu, sq, o);
    }
    __shared__ float ss[8], ssq[8];
    if ((t & 31) == 0) { ss[t >> 5] = s; ssq[t >> 5] = sq; }
    __syncthreads();
    float tot = 0.f, totq = 0.f;
    #pragma unroll
    for (int w = 0; w < 8; w++) { tot += ss[w]; totq += ssq[w]; }
    float mean = tot * (1.0f / D_);
    float var  = totq * (1.0f / D_) - mean * mean;
    out[row * D_ + t] = (v - mean) * rsqrtf(var + LN_EPS) * g[t] + beta[t];
}

// ---------------- launch ----------------------------------------------------
extern "C" void kernel_launch(void* const* d_in, const int* in_sizes, int n_in,
                              void* d_out, int out_size)
{
    const float* embed     = (const float*)d_in[0];
    // d_in[1] = refer_bbox (unused)
    const float* dist      = (const float*)d_in[2];
    const float* query_pos = (const float*)d_in[3];
    const float* in_proj_w = (const float*)d_in[4];
    const float* in_proj_b = (const float*)d_in[5];
    const float* out_w     = (const float*)d_in[6];
    const float* out_b     = (const float*)d_in[7];
    const float* tau_w     = (const float*)d_in[8];
    const float* tau_b     = (const float*)d_in[9];
    const float* w1        = (const float*)d_in[10];
    const float* b1        = (const float*)d_in[11];
    const float* w2        = (const float*)d_in[12];
    const float* b2        = (const float*)d_in[13];
    const float* g1        = (const float*)d_in[14];
    const float* beta1     = (const float*)d_in[15];
    const float* g2        = (const float*)d_in[16];
    const float* beta2     = (const float*)d_in[17];
    float* out = (float*)d_out;

    float *p_qksum, *p_tau, *p_ctx, *p_x, *p_h, *p_y;
    __half *p_qkh, *p_vh;
    cudaGetSymbolAddress((void**)&p_qksum, g_qksum);
    cudaGetSymbolAddress((void**)&p_qkh,   g_qk_h);
    cudaGetSymbolAddress((void**)&p_vh,    g_v_h);
    cudaGetSymbolAddress((void**)&p_tau,   g_tau);
    cudaGetSymbolAddress((void**)&p_ctx,   g_ctx);
    cudaGetSymbolAddress((void**)&p_x,     g_x);
    cudaGetSymbolAddress((void**)&p_h,     g_h);
    cudaGetSymbolAddress((void**)&p_y,     g_y);

    const int pg_smem = (2 * 128 * PST + 2 * 64 * PST) * (int)sizeof(uint32_t); // 55296
    cudaFuncSetAttribute(pgemm_kernel, cudaFuncAttributeMaxDynamicSharedMemorySize, pg_smem);

    // 1. qksum = embed + query_pos
    addvec_kernel<<<ROWS * D_ / 4 / 256, 256>>>(embed, query_pos, p_qksum, ROWS * D_ / 4);
    // 2. [q|k] = qksum @ in_proj_w[0:512].T + b  -> fp16
    pgemm_kernel<<<dim3(512 / 64, ROWS / 128), 256, pg_smem>>>(
        p_qksum, in_proj_w, in_proj_b, p_qkh, ROWS, 512, D_, 0, 1);
    // 3. v = embed @ wv.T + bv -> fp16
    pgemm_kernel<<<dim3(D_ / 64, ROWS / 128), 256, pg_smem>>>(
        embed, in_proj_w + 512 * D_, in_proj_b + 512, p_vh, ROWS, D_, D_, 0, 1);
    // 4. tau
    tau_kernel<<<ROWS / 8, 256>>>(embed, tau_w, tau_b, p_tau);
    // 5. fp16 flash attention
    flash_attn_kernel<<<dim3(N_ / BQ, B_ * H_), 256>>>(p_qkh, p_vh, p_tau, dist, p_ctx);
    // 6. tgt = ctx @ out_w.T + out_b
    pgemm_kernel<<<dim3(D_ / 64, ROWS / 128), 256, pg_smem>>>(
        p_ctx, out_w, out_b, p_y, ROWS, D_, D_, 0, 0);
    // 7. x = LN1(embed + tgt)
    add_ln_kernel<<<ROWS, 256>>>(embed, p_y, g1, beta1, p_x);
    // 8. h = relu(x @ w1.T + b1)
    pgemm_kernel<<<dim3(FFN_ / 64, ROWS / 128), 256, pg_smem>>>(
        p_x, w1, b1, p_h, ROWS, FFN_, D_, 1, 0);
    // 9. y = h @ w2.T + b2
    pgemm_kernel<<<dim3(D_ / 64, ROWS / 128), 256, pg_smem>>>(
        p_h, w2, b2, p_y, ROWS, D_, FFN_, 0, 0);
    // 10. out = LN2(x + y)
    add_ln_kernel<<<ROWS, 256>>>(p_x, p_y, g2, beta2, out);
}

// round 8
// speedup vs baseline: 7.4721x; 1.1498x over previous
#include <cuda_runtime.h>
#include <cuda_fp16.h>
#include <math.h>
#include <stdint.h>

// Problem dims (fixed)
#define B_    4
#define N_    1024
#define D_    256
#define H_    8
#define HD_   32
#define FFN_  1024
#define ROWS  (B_*N_)          // 4096
#define LN_EPS 1e-5f

// ---------------- scratch (static device memory; no allocs) ----------------
__device__ __align__(16) __half g_qksum_h[ROWS*D_];    // fp16(embed+query_pos)
__device__ __align__(16) __half g_embed_h[ROWS*D_];    // fp16(embed)
__device__ __align__(16) __half g_ipw_h[3*D_*D_];      // fp16 in_proj_w (768x256)
__device__ __align__(16) __half g_outw_h[D_*D_];
__device__ __align__(16) __half g_w1_h[FFN_*D_];
__device__ __align__(16) __half g_w2_h[D_*FFN_];
__device__ __align__(16) __half g_tauw_h[H_*D_];
__device__ __align__(16) __half g_qk_h[ROWS*2*D_];     // [q(256)|k(256)] fp16
__device__ __align__(16) __half g_v_h [ROWS*D_];
__device__ __align__(16) __half g_ctx_h[ROWS*D_];
__device__ __align__(16) __half g_x_h[ROWS*D_];
__device__ __align__(16) __half g_hh [ROWS*FFN_];
__device__ float g_x[ROWS*D_];
__device__ float g_y[ROWS*D_];

// ---------------- helpers ---------------------------------------------------
__device__ __forceinline__ void mma16(float* c, const uint32_t* a, uint32_t b0, uint32_t b1) {
    asm volatile(
        "mma.sync.aligned.m16n8k16.row.col.f32.f16.f16.f32 "
        "{%0,%1,%2,%3}, {%4,%5,%6,%7}, {%8,%9}, {%0,%1,%2,%3};\n"
        : "+f"(c[0]), "+f"(c[1]), "+f"(c[2]), "+f"(c[3])
        : "r"(a[0]), "r"(a[1]), "r"(a[2]), "r"(a[3]), "r"(b0), "r"(b1));
}
__device__ __forceinline__ void ldsm4(uint32_t* r, uint32_t addr) {
    asm volatile("ldmatrix.sync.aligned.m8n8.x4.shared.b16 {%0,%1,%2,%3}, [%4];"
        : "=r"(r[0]), "=r"(r[1]), "=r"(r[2]), "=r"(r[3]) : "r"(addr));
}
__device__ __forceinline__ void ldsm4t(uint32_t* r, uint32_t addr) {
    asm volatile("ldmatrix.sync.aligned.m8n8.x4.trans.shared.b16 {%0,%1,%2,%3}, [%4];"
        : "=r"(r[0]), "=r"(r[1]), "=r"(r[2]), "=r"(r[3]) : "r"(addr));
}
__device__ __forceinline__ uint32_t packh2(float lo, float hi) {
    __half2 p = __floats2half2_rn(lo, hi);
    return *reinterpret_cast<uint32_t*>(&p);
}
__device__ __forceinline__ uint32_t smaddr(const void* p) {
    return (uint32_t)__cvta_generic_to_shared(p);
}
__device__ __forceinline__ void cp16(uint32_t dst, const void* src) {
    asm volatile("cp.async.cg.shared.global [%0], [%1], 16;\n" :: "r"(dst), "l"(src));
}
__device__ __forceinline__ void cpcommit() { asm volatile("cp.async.commit_group;\n" ::: "memory"); }
__device__ __forceinline__ void cpwait1()  { asm volatile("cp.async.wait_group 1;\n" ::: "memory"); }
__device__ __forceinline__ void cpwait0()  { asm volatile("cp.async.wait_group 0;\n" ::: "memory"); }

// ---------------- prep: qksum_h = h(embed+query_pos), embed_h = h(embed) ---
__global__ void prep_kernel(const float* __restrict__ e, const float* __restrict__ qp,
                            __half* __restrict__ qksh, __half* __restrict__ eh, int n4) {
    int i = blockIdx.x * blockDim.x + threadIdx.x;
    if (i < n4) {
        float4 ev = ((const float4*)e)[i];
        float4 qv = ((const float4*)qp)[i];
        __half2 s01 = __floats2half2_rn(ev.x + qv.x, ev.y + qv.y);
        __half2 s23 = __floats2half2_rn(ev.z + qv.z, ev.w + qv.w);
        __half2 e01 = __floats2half2_rn(ev.x, ev.y);
        __half2 e23 = __floats2half2_rn(ev.z, ev.w);
        uint2 su = {*(uint32_t*)&s01, *(uint32_t*)&s23};
        uint2 eu = {*(uint32_t*)&e01, *(uint32_t*)&e23};
        ((uint2*)qksh)[i] = su;
        ((uint2*)eh)[i]   = eu;
    }
}

// ---------------- weight convert (all fp32 weights -> fp16, one kernel) ----
#define S0 49152   // in_proj_w 768*256/4
#define S1 (S0+16384)   // out_w
#define S2 (S1+65536)   // w1
#define S3 (S2+65536)   // w2
#define S4 (S3+512)     // tau_w
__global__ void convw_kernel(const float* __restrict__ ipw, const float* __restrict__ ow,
                             const float* __restrict__ w1, const float* __restrict__ w2,
                             const float* __restrict__ tw,
                             __half* __restrict__ ipwh, __half* __restrict__ owh,
                             __half* __restrict__ w1h, __half* __restrict__ w2h,
                             __half* __restrict__ twh) {
    int i = blockIdx.x * blockDim.x + threadIdx.x;
    const float* src; __half* dst; int k;
    if      (i < S0) { src = ipw; dst = ipwh; k = i; }
    else if (i < S1) { src = ow;  dst = owh;  k = i - S0; }
    else if (i < S2) { src = w1;  dst = w1h;  k = i - S1; }
    else if (i < S3) { src = w2;  dst = w2h;  k = i - S2; }
    else if (i < S4) { src = tw;  dst = twh;  k = i - S3; }
    else return;
    float4 v = ((const float4*)src)[k];
    __half2 a = __floats2half2_rn(v.x, v.y);
    __half2 b = __floats2half2_rn(v.z, v.w);
    uint2 u = {*(uint32_t*)&a, *(uint32_t*)&b};
    ((uint2*)dst)[k] = u;
}

// ---------------- fp16 pipelined GEMM: C = act(A @ W^T + bias) --------------
// A[M,K] fp16, W[Nc,K] fp16 row-major. BM=128, BN=64, BK=32, 256 threads.
#define HST 40
__global__ __launch_bounds__(256) void hgemm_kernel(
    const __half* __restrict__ A, const __half* __restrict__ W,
    const float* __restrict__ bias, void* __restrict__ Cv,
    int M, int Nc, int K, int relu, int half_out)
{
    __shared__ __half As[2][128 * HST];
    __shared__ __half Ws[2][64 * HST];
    const int tid = threadIdx.x;
    const int warp = tid >> 5, lane = tid & 31;
    const int grp = lane >> 2, t4 = lane & 3;
    const int wm = warp >> 1, wn = warp & 1;      // 4x2 warps; warp tile 32x32
    const int bm = blockIdx.y * 128, bn = blockIdx.x * 64;
    const int KT = K >> 5;
    const int r8a = ((lane >> 3) & 1) * 8 + (lane & 7);
    const int c8a = ((lane >> 4) & 1) * 8;
    const int r8b = ((lane >> 4) & 1) * 8 + (lane & 7);
    const int c8b = ((lane >> 3) & 1) * 8;

    // prefetch tile 0
    {
        #pragma unroll
        for (int rep = 0; rep < 2; rep++) {
            int idx = tid + rep * 256;
            int r = idx >> 2, seg = idx & 3;
            cp16(smaddr(&As[0][r * HST + seg * 8]), &A[(size_t)(bm + r) * K + seg * 8]);
        }
        int r = tid >> 2, seg = tid & 3;
        cp16(smaddr(&Ws[0][r * HST + seg * 8]), &W[(size_t)(bn + r) * K + seg * 8]);
        cpcommit();
    }

    float acc[2][4][4] = {};
    for (int kt = 0; kt < KT; kt++) {
        const int buf = kt & 1;
        if (kt + 1 < KT) {
            const int nb = buf ^ 1;
            const int k0 = (kt + 1) * 32;
            #pragma unroll
            for (int rep = 0; rep < 2; rep++) {
                int idx = tid + rep * 256;
                int r = idx >> 2, seg = idx & 3;
                cp16(smaddr(&As[nb][r * HST + seg * 8]), &A[(size_t)(bm + r) * K + k0 + seg * 8]);
            }
            int r = tid >> 2, seg = tid & 3;
            cp16(smaddr(&Ws[nb][r * HST + seg * 8]), &W[(size_t)(bn + r) * K + k0 + seg * 8]);
            cpcommit();
            cpwait1();
        } else {
            cpwait0();
        }
        __syncthreads();

        uint32_t af[2][2][4], bf[2][2][4];
        #pragma unroll
        for (int mf = 0; mf < 2; mf++)
            #pragma unroll
            for (int s = 0; s < 2; s++)
                ldsm4(af[mf][s], smaddr(&As[buf][(wm * 32 + mf * 16 + r8a) * HST + s * 16 + c8a]));
        #pragma unroll
        for (int nb2 = 0; nb2 < 2; nb2++)
            #pragma unroll
            for (int s = 0; s < 2; s++)
                ldsm4(bf[nb2][s], smaddr(&Ws[buf][(wn * 32 + nb2 * 16 + r8b) * HST + s * 16 + c8b]));
        #pragma unroll
        for (int mf = 0; mf < 2; mf++)
            #pragma unroll
            for (int nb2 = 0; nb2 < 2; nb2++)
                #pragma unroll
                for (int s = 0; s < 2; s++) {
                    mma16(acc[mf][2 * nb2],     af[mf][s], bf[nb2][s][0], bf[nb2][s][1]);
                    mma16(acc[mf][2 * nb2 + 1], af[mf][s], bf[nb2][s][2], bf[nb2][s][3]);
                }
        __syncthreads();
    }

    #pragma unroll
    for (int mf = 0; mf < 2; mf++) {
        int r0 = bm + wm * 32 + mf * 16 + grp;
        #pragma unroll
        for (int nf = 0; nf < 4; nf++) {
            int c0 = bn + wn * 32 + (nf >> 1) * 16 + (nf & 1) * 8 + 2 * t4;
            float b0v = bias[c0], b1v = bias[c0 + 1];
            float v0 = acc[mf][nf][0] + b0v, v1 = acc[mf][nf][1] + b1v;
            float v2 = acc[mf][nf][2] + b0v, v3 = acc[mf][nf][3] + b1v;
            if (relu) {
                v0 = fmaxf(v0, 0.f); v1 = fmaxf(v1, 0.f);
                v2 = fmaxf(v2, 0.f); v3 = fmaxf(v3, 0.f);
            }
            if (half_out) {
                __half* Ch = (__half*)Cv;
                *(__half2*)&Ch[(size_t)r0 * Nc + c0]       = __floats2half2_rn(v0, v1);
                *(__half2*)&Ch[(size_t)(r0 + 8) * Nc + c0] = __floats2half2_rn(v2, v3);
            } else {
                float* C = (float*)Cv;
                float2 p0 = {v0, v1}, p1 = {v2, v3};
                *(float2*)&C[(size_t)r0 * Nc + c0] = p0;
                *(float2*)&C[(size_t)(r0 + 8) * Nc + c0] = p1;
            }
        }
    }
}

// ---------------- fp16 flash attention (tau fused in prologue) --------------
#define BQ 128
#define JT 64
#define HSTR 40
#define NTILES (N_/JT)
__global__ __launch_bounds__(256, 2) void flash_attn_kernel(
    const __half* __restrict__ qh, const __half* __restrict__ vh,
    const __half* __restrict__ eh, const __half* __restrict__ twh,
    const float* __restrict__ tbias, const float* __restrict__ dist,
    __half* __restrict__ ctxh)
{
    __shared__ __half Qs[BQ * HSTR];
    __shared__ __half Ks[2][JT * HSTR];
    __shared__ __half Vs[2][JT * HSTR];
    __shared__ __half tws[D_];
    __shared__ float taus[BQ];

    const int bh = blockIdx.y;
    const int b = bh >> 3, h = bh & 7;
    const int i0 = blockIdx.x * BQ;
    const int tid = threadIdx.x;
    const int warp = tid >> 5, lane = tid & 31;
    const int grp = lane >> 2, t4 = lane & 3;
    const int wb = warp * 16;
    const int row_a = wb + grp, row_b = row_a + 8;

    const int r8a = ((lane >> 3) & 1) * 8 + (lane & 7);
    const int c8a = ((lane >> 4) & 1) * 8;
    const int r8b = ((lane >> 4) & 1) * 8 + (lane & 7);
    const int c8b = ((lane >> 3) & 1) * 8;

    // stage Q + K/V tile 0 (one cp.async group)
    {
        #pragma unroll
        for (int rep = 0; rep < 2; rep++) {
            int idx = tid + rep * 256;
            int r = idx >> 2, seg = idx & 3;
            cp16(smaddr(&Qs[r * HSTR + seg * 8]),
                 &qh[(size_t)(b * N_ + i0 + r) * (2 * D_) + h * HD_ + seg * 8]);
        }
        int r = tid >> 2, seg = tid & 3;
        cp16(smaddr(&Ks[0][r * HSTR + seg * 8]),
             &qh[(size_t)(b * N_ + r) * (2 * D_) + D_ + h * HD_ + seg * 8]);
        cp16(smaddr(&Vs[0][r * HSTR + seg * 8]),
             &vh[(size_t)(b * N_ + r) * D_ + h * HD_ + seg * 8]);
        cpcommit();
    }

    // ---- tau for this CTA's 128 rows (hidden behind cp.async) ----
    tws[tid] = twh[h * D_ + tid];
    __syncthreads();
    {
        const int trow = tid >> 1, thalf = tid & 1;
        const __half2* e2 = (const __half2*)&eh[(size_t)(b * N_ + i0 + trow) * D_ + thalf * 128];
        const __half2* w2 = (const __half2*)&tws[thalf * 128];
        float s = 0.f;
        #pragma unroll
        for (int k = 0; k < 64; k++) {
            float2 ef = __half22float2(e2[k]);
            float2 wf = __half22float2(w2[k]);
            s += ef.x * wf.x + ef.y * wf.y;
        }
        s += __shfl_xor_sync(0xffffffffu, s, 1);
        if (thalf == 0) taus[trow] = s + tbias[h];
    }
    __syncthreads();

    const float tau_a = taus[row_a];
    const float tau_b2 = taus[row_b];
    const float scale = 0.17677669529663688f;   // 1/sqrt(32)
    float m_a = -1e30f, m_b = -1e30f, l_a = 0.f, l_b = 0.f;
    float O[4][4] = {};
    uint32_t qa[2][4];

    for (int t = 0; t < NTILES; t++) {
        const int buf = t & 1;
        if (t + 1 < NTILES) {
            const int nb = buf ^ 1;
            int r = tid >> 2, seg = tid & 3;
            int j1 = (t + 1) * JT;
            cp16(smaddr(&Ks[nb][r * HSTR + seg * 8]),
                 &qh[(size_t)(b * N_ + j1 + r) * (2 * D_) + D_ + h * HD_ + seg * 8]);
            cp16(smaddr(&Vs[nb][r * HSTR + seg * 8]),
                 &vh[(size_t)(b * N_ + j1 + r) * D_ + h * HD_ + seg * 8]);
            cpcommit();
            cpwait1();
        } else {
            cpwait0();
        }
        __syncthreads();

        if (t == 0) {
            #pragma unroll
            for (int s = 0; s < 2; s++)
                ldsm4(qa[s], smaddr(&Qs[(wb + r8a) * HSTR + s * 16 + c8a]));
        }

        // ---- QK ----
        float acc[8][4] = {};
        #pragma unroll
        for (int s = 0; s < 2; s++) {
            #pragma unroll
            for (int nf2 = 0; nf2 < 4; nf2++) {
                uint32_t kb4[4];
                ldsm4(kb4, smaddr(&Ks[buf][(nf2 * 16 + r8b) * HSTR + s * 16 + c8b]));
                mma16(acc[2 * nf2],     qa[s], kb4[0], kb4[1]);
                mma16(acc[2 * nf2 + 1], qa[s], kb4[2], kb4[3]);
            }
        }

        // ---- bias + tile max ----
        const int j0 = t * JT;
        float mn_a = -1e30f, mn_b = -1e30f;
        #pragma unroll
        for (int nf = 0; nf < 8; nf++) {
            float2 da = *(const float2*)&dist[(size_t)(b * N_ + i0 + row_a) * N_ + j0 + nf * 8 + 2 * t4];
            float2 db = *(const float2*)&dist[(size_t)(b * N_ + i0 + row_b) * N_ + j0 + nf * 8 + 2 * t4];
            acc[nf][0] = acc[nf][0] * scale + da.x * tau_a;
            acc[nf][1] = acc[nf][1] * scale + da.y * tau_a;
            acc[nf][2] = acc[nf][2] * scale + db.x * tau_b2;
            acc[nf][3] = acc[nf][3] * scale + db.y * tau_b2;
            mn_a = fmaxf(mn_a, fmaxf(acc[nf][0], acc[nf][1]));
            mn_b = fmaxf(mn_b, fmaxf(acc[nf][2], acc[nf][3]));
        }
        mn_a = fmaxf(mn_a, __shfl_xor_sync(0xffffffffu, mn_a, 1));
        mn_a = fmaxf(mn_a, __shfl_xor_sync(0xffffffffu, mn_a, 2));
        mn_b = fmaxf(mn_b, __shfl_xor_sync(0xffffffffu, mn_b, 1));
        mn_b = fmaxf(mn_b, __shfl_xor_sync(0xffffffffu, mn_b, 2));

        const float mx_a = fmaxf(m_a, mn_a), mx_b = fmaxf(m_b, mn_b);
        const float al_a = __expf(m_a - mx_a), al_b = __expf(m_b - mx_b);
        m_a = mx_a; m_b = mx_b;

        float sum_a = 0.f, sum_b = 0.f;
        #pragma unroll
        for (int nf = 0; nf < 8; nf++) {
            acc[nf][0] = __expf(acc[nf][0] - mx_a);
            acc[nf][1] = __expf(acc[nf][1] - mx_a);
            acc[nf][2] = __expf(acc[nf][2] - mx_b);
            acc[nf][3] = __expf(acc[nf][3] - mx_b);
            sum_a += acc[nf][0] + acc[nf][1];
            sum_b += acc[nf][2] + acc[nf][3];
        }
        sum_a += __shfl_xor_sync(0xffffffffu, sum_a, 1);
        sum_a += __shfl_xor_sync(0xffffffffu, sum_a, 2);
        sum_b += __shfl_xor_sync(0xffffffffu, sum_b, 1);
        sum_b += __shfl_xor_sync(0xffffffffu, sum_b, 2);
        l_a = l_a * al_a + sum_a;
        l_b = l_b * al_b + sum_b;

        #pragma unroll
        for (int nf = 0; nf < 4; nf++) {
            O[nf][0] *= al_a; O[nf][1] *= al_a;
            O[nf][2] *= al_b; O[nf][3] *= al_b;
        }

        // ---- PV (P straight from accumulators) ----
        #pragma unroll
        for (int ks = 0; ks < 4; ks++) {
            uint32_t a[4];
            a[0] = packh2(acc[2 * ks][0],     acc[2 * ks][1]);
            a[1] = packh2(acc[2 * ks][2],     acc[2 * ks][3]);
            a[2] = packh2(acc[2 * ks + 1][0], acc[2 * ks + 1][1]);
            a[3] = packh2(acc[2 * ks + 1][2], acc[2 * ks + 1][3]);
            #pragma unroll
            for (int nfp = 0; nfp < 2; nfp++) {
                uint32_t vb4[4];
                ldsm4t(vb4, smaddr(&Vs[buf][(ks * 16 + r8a) * HSTR + nfp * 16 + c8a]));
                mma16(O[2 * nfp],     a, vb4[0], vb4[1]);
                mma16(O[2 * nfp + 1], a, vb4[2], vb4[3]);
            }
        }
        __syncthreads();
    }

    // epilogue: normalize, write fp16 ctx
    const float ia = 1.0f / l_a, ib = 1.0f / l_b;
    #pragma unroll
    for (int nf = 0; nf < 4; nf++) {
        *(__half2*)&ctxh[(size_t)(b * N_ + i0 + row_a) * D_ + h * HD_ + nf * 8 + 2 * t4]
            = __floats2half2_rn(O[nf][0] * ia, O[nf][1] * ia);
        *(__half2*)&ctxh[(size_t)(b * N_ + i0 + row_b) * D_ + h * HD_ + nf * 8 + 2 * t4]
            = __floats2half2_rn(O[nf][2] * ib, O[nf][3] * ib);
    }
}

// ---------------- fused add + layernorm (+ optional fp16 copy) --------------
__global__ __launch_bounds__(256) void add_ln_kernel(
    const float* __restrict__ A, const float* __restrict__ Bv,
    const float* __restrict__ g, const float* __restrict__ beta,
    float* __restrict__ out, __half* __restrict__ outh)
{
    const int row = blockIdx.x;
    const int t = threadIdx.x;
    float v = A[row * D_ + t] + Bv[row * D_ + t];
    float s = v, sq = v * v;
    #pragma unroll
    for (int o = 16; o; o >>= 1) {
        s  += __shfl_xor_sync(0xffffffffu, s,  o);
        sq += __shfl_xor_sync(0xffffffffu, sq, o);
    }
    __shared__ float ss[8], ssq[8];
    if ((t & 31) == 0) { ss[t >> 5] = s; ssq[t >> 5] = sq; }
    __syncthreads();
    float tot = 0.f, totq = 0.f;
    #pragma unroll
    for (int w = 0; w < 8; w++) { tot += ss[w]; totq += ssq[w]; }
    float mean = tot * (1.0f / D_);
    float var  = totq * (1.0f / D_) - mean * mean;
    float r = (v - mean) * rsqrtf(var + LN_EPS) * g[t] + beta[t];
    out[row * D_ + t] = r;
    if (outh) outh[row * D_ + t] = __float2half(r);
}

// ---------------- launch ----------------------------------------------------
extern "C" void kernel_launch(void* const* d_in, const int* in_sizes, int n_in,
                              void* d_out, int out_size)
{
    const float* embed     = (const float*)d_in[0];
    // d_in[1] = refer_bbox (unused)
    const float* dist      = (const float*)d_in[2];
    const float* query_pos = (const float*)d_in[3];
    const float* in_proj_w = (const float*)d_in[4];
    const float* in_proj_b = (const float*)d_in[5];
    const float* out_w     = (const float*)d_in[6];
    const float* out_b     = (const float*)d_in[7];
    const float* tau_w     = (const float*)d_in[8];
    const float* tau_b     = (const float*)d_in[9];
    const float* w1        = (const float*)d_in[10];
    const float* b1        = (const float*)d_in[11];
    const float* w2        = (const float*)d_in[12];
    const float* b2        = (const float*)d_in[13];
    const float* g1        = (const float*)d_in[14];
    const float* beta1     = (const float*)d_in[15];
    const float* g2        = (const float*)d_in[16];
    const float* beta2     = (const float*)d_in[17];
    float* out = (float*)d_out;

    __half *p_qksh, *p_eh, *p_ipwh, *p_owh, *p_w1h, *p_w2h, *p_twh;
    __half *p_qkh, *p_vh, *p_ctxh, *p_xh, *p_hh;
    float *p_x, *p_y;
    cudaGetSymbolAddress((void**)&p_qksh, g_qksum_h);
    cudaGetSymbolAddress((void**)&p_eh,   g_embed_h);
    cudaGetSymbolAddress((void**)&p_ipwh, g_ipw_h);
    cudaGetSymbolAddress((void**)&p_owh,  g_outw_h);
    cudaGetSymbolAddress((void**)&p_w1h,  g_w1_h);
    cudaGetSymbolAddress((void**)&p_w2h,  g_w2_h);
    cudaGetSymbolAddress((void**)&p_twh,  g_tauw_h);
    cudaGetSymbolAddress((void**)&p_qkh,  g_qk_h);
    cudaGetSymbolAddress((void**)&p_vh,   g_v_h);
    cudaGetSymbolAddress((void**)&p_ctxh, g_ctx_h);
    cudaGetSymbolAddress((void**)&p_xh,   g_x_h);
    cudaGetSymbolAddress((void**)&p_hh,   g_hh);
    cudaGetSymbolAddress((void**)&p_x,    g_x);
    cudaGetSymbolAddress((void**)&p_y,    g_y);

    // 1. prep: qksum_h, embed_h
    prep_kernel<<<ROWS * D_ / 4 / 256, 256>>>(embed, query_pos, p_qksh, p_eh, ROWS * D_ / 4);
    // 2. weight convert (fp32 -> fp16)
    convw_kernel<<<S4 / 256, 256>>>(in_proj_w, out_w, w1, w2, tau_w,
                                    p_ipwh, p_owh, p_w1h, p_w2h, p_twh);
    // 3. [q|k] = qksum @ Wqk^T + b -> fp16
    hgemm_kernel<<<dim3(512 / 64, ROWS / 128), 256>>>(
        p_qksh, p_ipwh, in_proj_b, p_qkh, ROWS, 512, D_, 0, 1);
    // 4. v = embed @ wv^T + bv -> fp16
    hgemm_kernel<<<dim3(D_ / 64, ROWS / 128), 256>>>(
        p_eh, p_ipwh + 512 * D_, in_proj_b + 512, p_vh, ROWS, D_, D_, 0, 1);
    // 5. flash attention (tau fused) -> ctx fp16
    flash_attn_kernel<<<dim3(N_ / BQ, B_ * H_), 256>>>(
        p_qkh, p_vh, p_eh, p_twh, tau_b, dist, p_ctxh);
    // 6. tgt = ctx @ out_w^T + out_b -> fp32
    hgemm_kernel<<<dim3(D_ / 64, ROWS / 128), 256>>>(
        p_ctxh, p_owh, out_b, p_y, ROWS, D_, D_, 0, 0);
    // 7. x = LN1(embed + tgt) -> fp32 + fp16
    add_ln_kernel<<<ROWS, 256>>>(embed, p_y, g1, beta1, p_x, p_xh);
    // 8. h = relu(x @ w1^T + b1) -> fp16
    hgemm_kernel<<<dim3(FFN_ / 64, ROWS / 128), 256>>>(
        p_xh, p_w1h, b1, p_hh, ROWS, FFN_, D_, 1, 1);
    // 9. y = h @ w2^T + b2 -> fp32
    hgemm_kernel<<<dim3(D_ / 64, ROWS / 128), 256>>>(
        p_hh, p_w2h, b2, p_y, ROWS, D_, FFN_, 0, 0);
    // 10. out = LN2(x + y)
    add_ln_kernel<<<ROWS, 256>>>(p_x, p_y, g2, beta2, out, nullptr);
}

// round 10
// speedup vs baseline: 7.6805x; 1.0279x over previous
#include <cuda_runtime.h>
#include <cuda_fp16.h>
#include <math.h>
#include <stdint.h>

// Problem dims (fixed)
#define B_    4
#define N_    1024
#define D_    256
#define H_    8
#define HD_   32
#define FFN_  1024
#define ROWS  (B_*N_)          // 4096
#define LN_EPS 1e-5f

// ---------------- scratch (static device memory; no allocs) ----------------
__device__ __align__(16) __half g_qksum_h[ROWS*D_];    // fp16(embed+query_pos)
__device__ __align__(16) __half g_embed_h[ROWS*D_];    // fp16(embed)
__device__ __align__(16) __half g_ipw_h[3*D_*D_];      // fp16 in_proj_w (768x256)
__device__ __align__(16) __half g_outw_h[D_*D_];
__device__ __align__(16) __half g_w1_h[FFN_*D_];
__device__ __align__(16) __half g_w2_h[D_*FFN_];
__device__ __align__(16) __half g_tauw_h[H_*D_];
__device__ __align__(16) __half g_qk_h[ROWS*2*D_];     // [q(256)|k(256)] fp16
__device__ __align__(16) __half g_v_h [ROWS*D_];
__device__ __align__(16) __half g_ctx_h[ROWS*D_];
__device__ __align__(16) __half g_x_h[ROWS*D_];
__device__ __align__(16) __half g_hh [ROWS*FFN_];
__device__ float g_x[ROWS*D_];
__device__ float g_y[ROWS*D_];

// ---------------- helpers ---------------------------------------------------
__device__ __forceinline__ void mma16(float* c, const uint32_t* a, uint32_t b0, uint32_t b1) {
    asm volatile(
        "mma.sync.aligned.m16n8k16.row.col.f32.f16.f16.f32 "
        "{%0,%1,%2,%3}, {%4,%5,%6,%7}, {%8,%9}, {%0,%1,%2,%3};\n"
        : "+f"(c[0]), "+f"(c[1]), "+f"(c[2]), "+f"(c[3])
        : "r"(a[0]), "r"(a[1]), "r"(a[2]), "r"(a[3]), "r"(b0), "r"(b1));
}
__device__ __forceinline__ void ldsm4(uint32_t* r, uint32_t addr) {
    asm volatile("ldmatrix.sync.aligned.m8n8.x4.shared.b16 {%0,%1,%2,%3}, [%4];"
        : "=r"(r[0]), "=r"(r[1]), "=r"(r[2]), "=r"(r[3]) : "r"(addr));
}
__device__ __forceinline__ void ldsm4t(uint32_t* r, uint32_t addr) {
    asm volatile("ldmatrix.sync.aligned.m8n8.x4.trans.shared.b16 {%0,%1,%2,%3}, [%4];"
        : "=r"(r[0]), "=r"(r[1]), "=r"(r[2]), "=r"(r[3]) : "r"(addr));
}
__device__ __forceinline__ uint32_t packh2(float lo, float hi) {
    __half2 p = __floats2half2_rn(lo, hi);
    return *reinterpret_cast<uint32_t*>(&p);
}
__device__ __forceinline__ uint32_t smaddr(const void* p) {
    return (uint32_t)__cvta_generic_to_shared(p);
}
__device__ __forceinline__ void cp16(uint32_t dst, const void* src) {
    asm volatile("cp.async.cg.shared.global [%0], [%1], 16;\n" :: "r"(dst), "l"(src));
}
__device__ __forceinline__ void cpcommit() { asm volatile("cp.async.commit_group;\n" ::: "memory"); }
__device__ __forceinline__ void cpwait1()  { asm volatile("cp.async.wait_group 1;\n" ::: "memory"); }
__device__ __forceinline__ void cpwait0()  { asm volatile("cp.async.wait_group 0;\n" ::: "memory"); }

#define HST 40

// ---------------- prep + weight convert (single launch) ---------------------
#define NP (ROWS*D_/4)       // 262144 float4 elements for prep
#define S0 49152             // in_proj_w 768*256/4
#define S1 (S0+16384)        // out_w
#define S2 (S1+65536)        // w1
#define S3 (S2+65536)        // w2
#define S4 (S3+512)          // tau_w
__global__ void prepconv_kernel(
    const float* __restrict__ e, const float* __restrict__ qp,
    __half* __restrict__ qksh, __half* __restrict__ eh,
    const float* __restrict__ ipw, const float* __restrict__ ow,
    const float* __restrict__ w1, const float* __restrict__ w2,
    const float* __restrict__ tw,
    __half* __restrict__ ipwh, __half* __restrict__ owh,
    __half* __restrict__ w1h, __half* __restrict__ w2h,
    __half* __restrict__ twh)
{
    int i = blockIdx.x * blockDim.x + threadIdx.x;
    if (i < NP) {
        float4 ev = ((const float4*)e)[i];
        float4 qv = ((const float4*)qp)[i];
        __half2 s01 = __floats2half2_rn(ev.x + qv.x, ev.y + qv.y);
        __half2 s23 = __floats2half2_rn(ev.z + qv.z, ev.w + qv.w);
        __half2 e01 = __floats2half2_rn(ev.x, ev.y);
        __half2 e23 = __floats2half2_rn(ev.z, ev.w);
        uint2 su = {*(uint32_t*)&s01, *(uint32_t*)&s23};
        uint2 eu = {*(uint32_t*)&e01, *(uint32_t*)&e23};
        ((uint2*)qksh)[i] = su;
        ((uint2*)eh)[i]   = eu;
        return;
    }
    int j = i - NP;
    const float* src; __half* dst; int k;
    if      (j < S0) { src = ipw; dst = ipwh; k = j; }
    else if (j < S1) { src = ow;  dst = owh;  k = j - S0; }
    else if (j < S2) { src = w1;  dst = w1h;  k = j - S1; }
    else if (j < S3) { src = w2;  dst = w2h;  k = j - S2; }
    else if (j < S4) { src = tw;  dst = twh;  k = j - S3; }
    else return;
    float4 v = ((const float4*)src)[k];
    __half2 a = __floats2half2_rn(v.x, v.y);
    __half2 b = __floats2half2_rn(v.z, v.w);
    uint2 u = {*(uint32_t*)&a, *(uint32_t*)&b};
    ((uint2*)dst)[k] = u;
}

// ---------------- 64x64 fp16 GEMM body (3-stage cp.async) -------------------
// A[M,K] fp16 (lda=K), Wrow = W + bn*K, biasc = bias + cn. C col base = cn.
__device__ __forceinline__ void gemm64_body(
    const __half* __restrict__ A, const __half* __restrict__ Wrow,
    const float* __restrict__ biasc, const float* __restrict__ resid,
    void* __restrict__ Cv, int ldC, int bm, int cn,
    int K, int relu, int half_out, __half* As, __half* Ws)
{
    const int tid = threadIdx.x;
    const int warp = tid >> 5, lane = tid & 31;
    const int grp = lane >> 2, t4 = lane & 3;
    const int wm = warp >> 1, wn = warp & 1;
    const int KT = K >> 5;
    const int r8a = ((lane >> 3) & 1) * 8 + (lane & 7);
    const int c8a = ((lane >> 4) & 1) * 8;
    const int r8b = ((lane >> 4) & 1) * 8 + (lane & 7);
    const int c8b = ((lane >> 3) & 1) * 8;
    const int lr = tid >> 2, lseg = tid & 3;   // load row pair base
    const int lr2 = lr + 32;

    // prefetch k-tiles 0 and 1
    #pragma unroll
    for (int p = 0; p < 2; p++) {
        if (p < KT) {
            const int k0 = p * 32;
            cp16(smaddr(&As[p * 64 * HST + lr * HST + lseg * 8]),  &A[(size_t)(bm + lr) * K + k0 + lseg * 8]);
            cp16(smaddr(&As[p * 64 * HST + lr2 * HST + lseg * 8]), &A[(size_t)(bm + lr2) * K + k0 + lseg * 8]);
            cp16(smaddr(&Ws[p * 64 * HST + lr * HST + lseg * 8]),  &Wrow[(size_t)lr * K + k0 + lseg * 8]);
            cp16(smaddr(&Ws[p * 64 * HST + lr2 * HST + lseg * 8]), &Wrow[(size_t)lr2 * K + k0 + lseg * 8]);
            cpcommit();
        }
    }

    float acc[2][4][4] = {};
    for (int kt = 0; kt < KT; kt++) {
        const int st = kt % 3;
        if (kt + 1 < KT) cpwait1(); else cpwait0();
        __syncthreads();
        if (kt + 2 < KT) {
            const int ns = (kt + 2) % 3;
            const int k0 = (kt + 2) * 32;
            cp16(smaddr(&As[ns * 64 * HST + lr * HST + lseg * 8]),  &A[(size_t)(bm + lr) * K + k0 + lseg * 8]);
            cp16(smaddr(&As[ns * 64 * HST + lr2 * HST + lseg * 8]), &A[(size_t)(bm + lr2) * K + k0 + lseg * 8]);
            cp16(smaddr(&Ws[ns * 64 * HST + lr * HST + lseg * 8]),  &Wrow[(size_t)lr * K + k0 + lseg * 8]);
            cp16(smaddr(&Ws[ns * 64 * HST + lr2 * HST + lseg * 8]), &Wrow[(size_t)lr2 * K + k0 + lseg * 8]);
            cpcommit();
        }
        __half* Ab = &As[st * 64 * HST];
        __half* Wb = &Ws[st * 64 * HST];
        uint32_t af[2][2][4], bf[2][2][4];
        #pragma unroll
        for (int mf = 0; mf < 2; mf++)
            #pragma unroll
            for (int s = 0; s < 2; s++)
                ldsm4(af[mf][s], smaddr(&Ab[(wm * 32 + mf * 16 + r8a) * HST + s * 16 + c8a]));
        #pragma unroll
        for (int nb2 = 0; nb2 < 2; nb2++)
            #pragma unroll
            for (int s = 0; s < 2; s++)
                ldsm4(bf[nb2][s], smaddr(&Wb[(wn * 32 + nb2 * 16 + r8b) * HST + s * 16 + c8b]));
        #pragma unroll
        for (int mf = 0; mf < 2; mf++)
            #pragma unroll
            for (int nb2 = 0; nb2 < 2; nb2++)
                #pragma unroll
                for (int s = 0; s < 2; s++) {
                    mma16(acc[mf][2 * nb2],     af[mf][s], bf[nb2][s][0], bf[nb2][s][1]);
                    mma16(acc[mf][2 * nb2 + 1], af[mf][s], bf[nb2][s][2], bf[nb2][s][3]);
                }
        __syncthreads();
    }

    #pragma unroll
    for (int mf = 0; mf < 2; mf++) {
        int r0 = bm + wm * 32 + mf * 16 + grp;
        #pragma unroll
        for (int nf = 0; nf < 4; nf++) {
            int cl = wn * 32 + (nf >> 1) * 16 + (nf & 1) * 8 + 2 * t4;
            int c0 = cn + cl;
            float b0v = biasc[cl], b1v = biasc[cl + 1];
            float v0 = acc[mf][nf][0] + b0v, v1 = acc[mf][nf][1] + b1v;
            float v2 = acc[mf][nf][2] + b0v, v3 = acc[mf][nf][3] + b1v;
            if (resid) {
                v0 += resid[(size_t)r0 * ldC + c0];
                v1 += resid[(size_t)r0 * ldC + c0 + 1];
                v2 += resid[(size_t)(r0 + 8) * ldC + c0];
                v3 += resid[(size_t)(r0 + 8) * ldC + c0 + 1];
            }
            if (relu) {
                v0 = fmaxf(v0, 0.f); v1 = fmaxf(v1, 0.f);
                v2 = fmaxf(v2, 0.f); v3 = fmaxf(v3, 0.f);
            }
            if (half_out) {
                __half* Ch = (__half*)Cv;
                *(__half2*)&Ch[(size_t)r0 * ldC + c0]       = __floats2half2_rn(v0, v1);
                *(__half2*)&Ch[(size_t)(r0 + 8) * ldC + c0] = __floats2half2_rn(v2, v3);
            } else {
                float* C = (float*)Cv;
                float2 p0 = {v0, v1}, p1 = {v2, v3};
                *(float2*)&C[(size_t)r0 * ldC + c0] = p0;
                *(float2*)&C[(size_t)(r0 + 8) * ldC + c0] = p1;
            }
        }
    }
}

__global__ __launch_bounds__(128) void hgemm64_kernel(
    const __half* __restrict__ A, const __half* __restrict__ W,
    const float* __restrict__ bias, const float* __restrict__ resid,
    void* __restrict__ Cv, int Nc, int K, int relu, int half_out)
{
    __shared__ __half As[3][64 * HST];
    __shared__ __half Ws[3][64 * HST];
    const int bm = blockIdx.y * 64, bn = blockIdx.x * 64;
    gemm64_body(A, W + (size_t)bn * K, bias + bn, resid, Cv, Nc, bm, bn,
                K, relu, half_out, &As[0][0], &Ws[0][0]);
}

// fused QKV: bx<8 -> [q|k] from qksum; bx>=8 -> v from embed
__global__ __launch_bounds__(128) void qkv_kernel(
    const __half* __restrict__ qksh, const __half* __restrict__ eh,
    const __half* __restrict__ ipwh, const float* __restrict__ ipb,
    __half* __restrict__ qkh, __half* __restrict__ vh)
{
    __shared__ __half As[3][64 * HST];
    __shared__ __half Ws[3][64 * HST];
    const int bx = blockIdx.x, bm = blockIdx.y * 64;
    if (bx < 8) {
        const int bn = bx * 64;
        gemm64_body(qksh, ipwh + (size_t)bn * D_, ipb + bn, nullptr, qkh, 512, bm, bn,
                    D_, 0, 1, &As[0][0], &Ws[0][0]);
    } else {
        const int bn = (bx - 8) * 64;
        gemm64_body(eh, ipwh + (size_t)(512 + bn) * D_, ipb + 512 + bn, nullptr, vh, 256, bm, bn,
                    D_, 0, 1, &As[0][0], &Ws[0][0]);
    }
}

// ---------------- fp16 flash attention (tau fused in prologue) --------------
#define BQ 128
#define JT 64
#define HSTR 40
#define NTILES (N_/JT)
__global__ __launch_bounds__(256, 2) void flash_attn_kernel(
    const __half* __restrict__ qh, const __half* __restrict__ vh,
    const __half* __restrict__ eh, const __half* __restrict__ twh,
    const float* __restrict__ tbias, const float* __restrict__ dist,
    __half* __restrict__ ctxh)
{
    __shared__ __half Qs[BQ * HSTR];
    __shared__ __half Ks[2][JT * HSTR];
    __shared__ __half Vs[2][JT * HSTR];
    __shared__ __half tws[D_];
    __shared__ float taus[BQ];

    const int bh = blockIdx.y;
    const int b = bh >> 3, h = bh & 7;
    const int i0 = blockIdx.x * BQ;
    const int tid = threadIdx.x;
    const int warp = tid >> 5, lane = tid & 31;
    const int grp = lane >> 2, t4 = lane & 3;
    const int wb = warp * 16;
    const int row_a = wb + grp, row_b = row_a + 8;

    const int r8a = ((lane >> 3) & 1) * 8 + (lane & 7);
    const int c8a = ((lane >> 4) & 1) * 8;
    const int r8b = ((lane >> 4) & 1) * 8 + (lane & 7);
    const int c8b = ((lane >> 3) & 1) * 8;

    // stage Q + K/V tile 0 (one cp.async group)
    {
        #pragma unroll
        for (int rep = 0; rep < 2; rep++) {
            int idx = tid + rep * 256;
            int r = idx >> 2, seg = idx & 3;
            cp16(smaddr(&Qs[r * HSTR + seg * 8]),
                 &qh[(size_t)(b * N_ + i0 + r) * (2 * D_) + h * HD_ + seg * 8]);
        }
        int r = tid >> 2, seg = tid & 3;
        cp16(smaddr(&Ks[0][r * HSTR + seg * 8]),
             &qh[(size_t)(b * N_ + r) * (2 * D_) + D_ + h * HD_ + seg * 8]);
        cp16(smaddr(&Vs[0][r * HSTR + seg * 8]),
             &vh[(size_t)(b * N_ + r) * D_ + h * HD_ + seg * 8]);
        cpcommit();
    }

    // ---- tau for this CTA's 128 rows (hidden behind cp.async) ----
    tws[tid] = twh[h * D_ + tid];
    __syncthreads();
    {
        const int trow = tid >> 1, thalf = tid & 1;
        const __half2* e2 = (const __half2*)&eh[(size_t)(b * N_ + i0 + trow) * D_ + thalf * 128];
        const __half2* w2 = (const __half2*)&tws[thalf * 128];
        float s = 0.f;
        #pragma unroll
        for (int k = 0; k < 64; k++) {
            float2 ef = __half22float2(e2[k]);
            float2 wf = __half22float2(w2[k]);
            s += ef.x * wf.x + ef.y * wf.y;
        }
        s += __shfl_xor_sync(0xffffffffu, s, 1);
        if (thalf == 0) taus[trow] = s + tbias[h];
    }
    __syncthreads();

    const float tau_a = taus[row_a];
    const float tau_b2 = taus[row_b];
    const float scale = 0.17677669529663688f;   // 1/sqrt(32)
    float m_a = -1e30f, m_b = -1e30f, l_a = 0.f, l_b = 0.f;
    float O[4][4] = {};
    uint32_t qa[2][4];

    for (int t = 0; t < NTILES; t++) {
        const int buf = t & 1;
        if (t + 1 < NTILES) {
            const int nb = buf ^ 1;
            int r = tid >> 2, seg = tid & 3;
            int j1 = (t + 1) * JT;
            cp16(smaddr(&Ks[nb][r * HSTR + seg * 8]),
                 &qh[(size_t)(b * N_ + j1 + r) * (2 * D_) + D_ + h * HD_ + seg * 8]);
            cp16(smaddr(&Vs[nb][r * HSTR + seg * 8]),
                 &vh[(size_t)(b * N_ + j1 + r) * D_ + h * HD_ + seg * 8]);
            cpcommit();
            cpwait1();
        } else {
            cpwait0();
        }
        __syncthreads();

        if (t == 0) {
            #pragma unroll
            for (int s = 0; s < 2; s++)
                ldsm4(qa[s], smaddr(&Qs[(wb + r8a) * HSTR + s * 16 + c8a]));
        }

        // ---- QK ----
        float acc[8][4] = {};
        #pragma unroll
        for (int s = 0; s < 2; s++) {
            #pragma unroll
            for (int nf2 = 0; nf2 < 4; nf2++) {
                uint32_t kb4[4];
                ldsm4(kb4, smaddr(&Ks[buf][(nf2 * 16 + r8b) * HSTR + s * 16 + c8b]));
                mma16(acc[2 * nf2],     qa[s], kb4[0], kb4[1]);
                mma16(acc[2 * nf2 + 1], qa[s], kb4[2], kb4[3]);
            }
        }

        // ---- bias + tile max ----
        const int j0 = t * JT;
        float mn_a = -1e30f, mn_b = -1e30f;
        #pragma unroll
        for (int nf = 0; nf < 8; nf++) {
            float2 da = *(const float2*)&dist[(size_t)(b * N_ + i0 + row_a) * N_ + j0 + nf * 8 + 2 * t4];
            float2 db = *(const float2*)&dist[(size_t)(b * N_ + i0 + row_b) * N_ + j0 + nf * 8 + 2 * t4];
            acc[nf][0] = acc[nf][0] * scale + da.x * tau_a;
            acc[nf][1] = acc[nf][1] * scale + da.y * tau_a;
            acc[nf][2] = acc[nf][2] * scale + db.x * tau_b2;
            acc[nf][3] = acc[nf][3] * scale + db.y * tau_b2;
            mn_a = fmaxf(mn_a, fmaxf(acc[nf][0], acc[nf][1]));
            mn_b = fmaxf(mn_b, fmaxf(acc[nf][2], acc[nf][3]));
        }
        mn_a = fmaxf(mn_a, __shfl_xor_sync(0xffffffffu, mn_a, 1));
        mn_a = fmaxf(mn_a, __shfl_xor_sync(0xffffffffu, mn_a, 2));
        mn_b = fmaxf(mn_b, __shfl_xor_sync(0xffffffffu, mn_b, 1));
        mn_b = fmaxf(mn_b, __shfl_xor_sync(0xffffffffu, mn_b, 2));

        const float mx_a = fmaxf(m_a, mn_a), mx_b = fmaxf(m_b, mn_b);
        const float al_a = __expf(m_a - mx_a), al_b = __expf(m_b - mx_b);
        m_a = mx_a; m_b = mx_b;

        float sum_a = 0.f, sum_b = 0.f;
        #pragma unroll
        for (int nf = 0; nf < 8; nf++) {
            acc[nf][0] = __expf(acc[nf][0] - mx_a);
            acc[nf][1] = __expf(acc[nf][1] - mx_a);
            acc[nf][2] = __expf(acc[nf][2] - mx_b);
            acc[nf][3] = __expf(acc[nf][3] - mx_b);
            sum_a += acc[nf][0] + acc[nf][1];
            sum_b += acc[nf][2] + acc[nf][3];
        }
        sum_a += __shfl_xor_sync(0xffffffffu, sum_a, 1);
        sum_a += __shfl_xor_sync(0xffffffffu, sum_a, 2);
        sum_b += __shfl_xor_sync(0xffffffffu, sum_b, 1);
        sum_b += __shfl_xor_sync(0xffffffffu, sum_b, 2);
        l_a = l_a * al_a + sum_a;
        l_b = l_b * al_b + sum_b;

        #pragma unroll
        for (int nf = 0; nf < 4; nf++) {
            O[nf][0] *= al_a; O[nf][1] *= al_a;
            O[nf][2] *= al_b; O[nf][3] *= al_b;
        }

        // ---- PV (P straight from accumulators) ----
        #pragma unroll
        for (int ks = 0; ks < 4; ks++) {
            uint32_t a[4];
            a[0] = packh2(acc[2 * ks][0],     acc[2 * ks][1]);
            a[1] = packh2(acc[2 * ks][2],     acc[2 * ks][3]);
            a[2] = packh2(acc[2 * ks + 1][0], acc[2 * ks + 1][1]);
            a[3] = packh2(acc[2 * ks + 1][2], acc[2 * ks + 1][3]);
            #pragma unroll
            for (int nfp = 0; nfp < 2; nfp++) {
                uint32_t vb4[4];
                ldsm4t(vb4, smaddr(&Vs[buf][(ks * 16 + r8a) * HSTR + nfp * 16 + c8a]));
                mma16(O[2 * nfp],     a, vb4[0], vb4[1]);
                mma16(O[2 * nfp + 1], a, vb4[2], vb4[3]);
            }
        }
        __syncthreads();
    }

    // epilogue: normalize, write fp16 ctx
    const float ia = 1.0f / l_a, ib = 1.0f / l_b;
    #pragma unroll
    for (int nf = 0; nf < 4; nf++) {
        *(__half2*)&ctxh[(size_t)(b * N_ + i0 + row_a) * D_ + h * HD_ + nf * 8 + 2 * t4]
            = __floats2half2_rn(O[nf][0] * ia, O[nf][1] * ia);
        *(__half2*)&ctxh[(size_t)(b * N_ + i0 + row_b) * D_ + h * HD_ + nf * 8 + 2 * t4]
            = __floats2half2_rn(O[nf][2] * ib, O[nf][3] * ib);
    }
}

// ---------------- layernorm (single input; residual pre-added) --------------
__global__ __launch_bounds__(256) void ln_kernel(
    const float* __restrict__ Y,
    const float* __restrict__ g, const float* __restrict__ beta,
    float* __restrict__ out, __half* __restrict__ outh)
{
    const int row = blockIdx.x;
    const int t = threadIdx.x;
    float v = Y[row * D_ + t];
    float s = v, sq = v * v;
    #pragma unroll
    for (int o = 16; o; o >>= 1) {
        s  += __shfl_xor_sync(0xffffffffu, s,  o);
        sq += __shfl_xor_sync(0xffffffffu, sq, o);
    }
    __shared__ float ss[8], ssq[8];
    if ((t & 31) == 0) { ss[t >> 5] = s; ssq[t >> 5] = sq; }
    __syncthreads();
    float tot = 0.f, totq = 0.f;
    #pragma unroll
    for (int w = 0; w < 8; w++) { tot += ss[w]; totq += ssq[w]; }
    float mean = tot * (1.0f / D_);
    float var  = totq * (1.0f / D_) - mean * mean;
    float r = (v - mean) * rsqrtf(var + LN_EPS) * g[t] + beta[t];
    out[row * D_ + t] = r;
    if (outh) outh[row * D_ + t] = __float2half(r);
}

// ---------------- launch ----------------------------------------------------
extern "C" void kernel_launch(void* const* d_in, const int* in_sizes, int n_in,
                              void* d_out, int out_size)
{
    const float* embed     = (const float*)d_in[0];
    // d_in[1] = refer_bbox (unused)
    const float* dist      = (const float*)d_in[2];
    const float* query_pos = (const float*)d_in[3];
    const float* in_proj_w = (const float*)d_in[4];
    const float* in_proj_b = (const float*)d_in[5];
    const float* out_w     = (const float*)d_in[6];
    const float* out_b     = (const float*)d_in[7];
    const float* tau_w     = (const float*)d_in[8];
    const float* tau_b     = (const float*)d_in[9];
    const float* w1        = (const float*)d_in[10];
    const float* b1        = (const float*)d_in[11];
    const float* w2        = (const float*)d_in[12];
    const float* b2        = (const float*)d_in[13];
    const float* g1        = (const float*)d_in[14];
    const float* beta1     = (const float*)d_in[15];
    const float* g2        = (const float*)d_in[16];
    const float* beta2     = (const float*)d_in[17];
    float* out = (float*)d_out;

    __half *p_qksh, *p_eh, *p_ipwh, *p_owh, *p_w1h, *p_w2h, *p_twh;
    __half *p_qkh, *p_vh, *p_ctxh, *p_xh, *p_hh;
    float *p_x, *p_y;
    cudaGetSymbolAddress((void**)&p_qksh, g_qksum_h);
    cudaGetSymbolAddress((void**)&p_eh,   g_embed_h);
    cudaGetSymbolAddress((void**)&p_ipwh, g_ipw_h);
    cudaGetSymbolAddress((void**)&p_owh,  g_outw_h);
    cudaGetSymbolAddress((void**)&p_w1h,  g_w1_h);
    cudaGetSymbolAddress((void**)&p_w2h,  g_w2_h);
    cudaGetSymbolAddress((void**)&p_twh,  g_tauw_h);
    cudaGetSymbolAddress((void**)&p_qkh,  g_qk_h);
    cudaGetSymbolAddress((void**)&p_vh,   g_v_h);
    cudaGetSymbolAddress((void**)&p_ctxh, g_ctx_h);
    cudaGetSymbolAddress((void**)&p_xh,   g_x_h);
    cudaGetSymbolAddress((void**)&p_hh,   g_hh);
    cudaGetSymbolAddress((void**)&p_x,    g_x);
    cudaGetSymbolAddress((void**)&p_y,    g_y);

    // 1. prep activations + convert all weights (one launch)
    prepconv_kernel<<<(NP + S4 + 255) / 256, 256>>>(
        embed, query_pos, p_qksh, p_eh,
        in_proj_w, out_w, w1, w2, tau_w,
        p_ipwh, p_owh, p_w1h, p_w2h, p_twh);
    // 2. fused QKV projection (768 CTAs)
    qkv_kernel<<<dim3(12, ROWS / 64), 128>>>(p_qksh, p_eh, p_ipwh, in_proj_b, p_qkh, p_vh);
    // 3. flash attention (tau fused) -> ctx fp16
    flash_attn_kernel<<<dim3(N_ / BQ, B_ * H_), 256>>>(
        p_qkh, p_vh, p_eh, p_twh, tau_b, dist, p_ctxh);
    // 4. y = embed + ctx @ out_w^T + out_b   (residual fused)
    hgemm64_kernel<<<dim3(D_ / 64, ROWS / 64), 128>>>(
        p_ctxh, p_owh, out_b, embed, p_y, D_, D_, 0, 0);
    // 5. x = LN1(y) -> fp32 + fp16
    ln_kernel<<<ROWS, 256>>>(p_y, g1, beta1, p_x, p_xh);
    // 6. h = relu(x @ w1^T + b1) -> fp16
    hgemm64_kernel<<<dim3(FFN_ / 64, ROWS / 64), 128>>>(
        p_xh, p_w1h, b1, nullptr, p_hh, FFN_, D_, 1, 1);
    // 7. y = x + h @ w2^T + b2   (residual fused)
    hgemm64_kernel<<<dim3(D_ / 64, ROWS / 64), 128>>>(
        p_hh, p_w2h, b2, p_x, p_y, D_, FFN_, 0, 0);
    // 8. out = LN2(y)
    ln_kernel<<<ROWS, 256>>>(p_y, g2, beta2, out, nullptr);
}